// round 1
// baseline (speedup 1.0000x reference)
#include <cuda_runtime.h>
#include <math.h>

// Problem constants (shapes fixed by the dataset)
#define NMAX 50000
#define EMAX 800000

// ---------------- scratch (static device globals; no allocation) ------------
__device__ float g_bufA[NMAX * 128];   // GEMM outputs / pre-agg features
__device__ float g_bufB[NMAX * 128];   // post-agg hidden / cluster hidden
__device__ float g_bufC[NMAX * 64];    // encoder output Z
__device__ float g_dinv[NMAX];         // 1/sqrt(deg) (deg includes self loop)
__device__ int   g_deg[NMAX];
__device__ int   g_off[NMAX + 1];
__device__ int   g_cur[NMAX];
__device__ int   g_csr[EMAX];

// ---------------- graph preprocessing ---------------------------------------
__global__ void zero_counts_kernel(int n) {
    int i = blockIdx.x * blockDim.x + threadIdx.x;
    if (i < n) { g_deg[i] = 0; g_cur[i] = 0; }
}

__global__ void hist_kernel(const int* __restrict__ col, int E) {
    int i = blockIdx.x * blockDim.x + threadIdx.x;
    if (i < E) atomicAdd(&g_deg[col[i]], 1);
}

// exclusive scan of g_deg -> g_off, plus dinv = rsqrt(deg+1). One block.
__global__ void scan_kernel(int n) {
    __shared__ int sh[1024];
    __shared__ int carry;
    int tid = threadIdx.x;
    if (tid == 0) carry = 0;
    __syncthreads();
    for (int base = 0; base < n; base += 1024) {
        int i = base + tid;
        int v = (i < n) ? g_deg[i] : 0;
        sh[tid] = v;
        __syncthreads();
        for (int d = 1; d < 1024; d <<= 1) {
            int t = (tid >= d) ? sh[tid - d] : 0;
            __syncthreads();
            sh[tid] += t;
            __syncthreads();
        }
        if (i < n) {
            g_off[i]  = carry + sh[tid] - v;
            g_dinv[i] = rsqrtf((float)(v + 1));
        }
        __syncthreads();
        if (tid == 0) carry += sh[1023];
        __syncthreads();
    }
    if (tid == 0) g_off[n] = carry;
}

__global__ void fill_csr_kernel(const int* __restrict__ ei, int E) {
    int i = blockIdx.x * blockDim.x + threadIdx.x;
    if (i < E) {
        int r = ei[i];       // source (x_j)
        int c = ei[E + i];   // target
        int p = atomicAdd(&g_cur[c], 1);
        g_csr[g_off[c] + p] = r;
    }
}

// ---------------- neighbor aggregation ---------------------------------------
// out[node] = relu( dinv[node] * (G[node] + sum_{nbr in csr(node)} G[nbr]) + bias )
// (G rows are already pre-scaled by dinv[source])
template <int F>
__global__ void agg_kernel(const float* __restrict__ G,
                           const float* __restrict__ bias,
                           float* __restrict__ out) {
    int node = blockIdx.x;
    int f = threadIdx.x;
    __shared__ int nb[F];
    int s = g_off[node], e = g_off[node + 1];
    float acc = G[(size_t)node * F + f];
    for (int j0 = s; j0 < e; j0 += F) {
        int cnt = min(F, e - j0);
        if (f < cnt) nb[f] = g_csr[j0 + f];
        __syncthreads();
        int t = 0;
        for (; t + 4 <= cnt; t += 4) {
            float v0 = G[(size_t)nb[t]     * F + f];
            float v1 = G[(size_t)nb[t + 1] * F + f];
            float v2 = G[(size_t)nb[t + 2] * F + f];
            float v3 = G[(size_t)nb[t + 3] * F + f];
            acc += v0; acc += v1; acc += v2; acc += v3;
        }
        for (; t < cnt; t++) acc += G[(size_t)nb[t] * F + f];
        __syncthreads();
    }
    float v = g_dinv[node] * acc + bias[f];
    out[(size_t)node * F + f] = fmaxf(v, 0.0f);
}

// ---------------- SGEMM: C[N,F] = A[N,K] @ B[K,F] with fused epilogue --------
// EPI 0: out = acc * g_dinv[row]          (vec unused)
// EPI 1: out = relu(acc + vec[col])
// EPI 2: out = acc + vec[col]
template <int K, int F, int EPI>
__global__ __launch_bounds__(256) void gemm_kernel(
    const float* __restrict__ A, const float* __restrict__ B,
    const float* __restrict__ vec, float* __restrict__ C, int N) {
    constexpr int BM = 128, BK = 32;
    constexpr int TM = 8, TN = F / 16;
    __shared__ float As[BK][BM];
    __shared__ float Bs[BK][F];

    int tid = threadIdx.x;            // 256 threads
    int tx = tid & 15;                // 16 col groups
    int ty = tid >> 4;                // 16 row groups
    int rowBase = blockIdx.x * BM;

    float acc[TM][TN];
#pragma unroll
    for (int i = 0; i < TM; i++)
#pragma unroll
        for (int j = 0; j < TN; j++) acc[i][j] = 0.0f;

    for (int kc = 0; kc < K; kc += BK) {
        // Load A tile (BM x BK), transposed into As[k][row]
#pragma unroll
        for (int q = 0; q < 4; q++) {
            int lin = tid + q * 256;      // 0..1023
            int r  = lin >> 3;            // 128 rows
            int qd = lin & 7;             // 8 float4 per row
            float4 v = make_float4(0.f, 0.f, 0.f, 0.f);
            int gr = rowBase + r;
            if (gr < N)
                v = *reinterpret_cast<const float4*>(&A[(size_t)gr * K + kc + qd * 4]);
            As[qd * 4 + 0][r] = v.x;
            As[qd * 4 + 1][r] = v.y;
            As[qd * 4 + 2][r] = v.z;
            As[qd * 4 + 3][r] = v.w;
        }
        // Load B tile (BK x F)
        constexpr int BQ = (BK * F / 4) / 256;  // float4s per thread
#pragma unroll
        for (int q = 0; q < BQ; q++) {
            int lin = tid + q * 256;
            int kk = lin / (F / 4);
            int cq = lin % (F / 4);
            float4 v = *reinterpret_cast<const float4*>(&B[(size_t)(kc + kk) * F + cq * 4]);
            *reinterpret_cast<float4*>(&Bs[kk][cq * 4]) = v;
        }
        __syncthreads();

#pragma unroll
        for (int kk = 0; kk < BK; kk++) {
            float a[TM], b[TN];
#pragma unroll
            for (int i = 0; i < TM; i++) a[i] = As[kk][ty * TM + i];
#pragma unroll
            for (int j = 0; j < TN; j++) b[j] = Bs[kk][tx * TN + j];
#pragma unroll
            for (int i = 0; i < TM; i++)
#pragma unroll
                for (int j = 0; j < TN; j++) acc[i][j] = fmaf(a[i], b[j], acc[i][j]);
        }
        __syncthreads();
    }

#pragma unroll
    for (int i = 0; i < TM; i++) {
        int gr = rowBase + ty * TM + i;
        if (gr >= N) continue;
        float rs = (EPI == 0) ? g_dinv[gr] : 1.0f;
#pragma unroll
        for (int j = 0; j < TN; j++) {
            int gc = tx * TN + j;
            float v = acc[i][j];
            if (EPI == 0) v *= rs;
            else {
                v += vec[gc];
                if (EPI == 1) v = fmaxf(v, 0.0f);
            }
            C[(size_t)gr * F + gc] = v;
        }
    }
}

// ---------------- L2 normalize rows of length 128 (in place) -----------------
__global__ void l2norm_kernel(float* __restrict__ z) {
    int r = blockIdx.x;
    int t = threadIdx.x;   // 128
    float v = z[(size_t)r * 128 + t];
    __shared__ float sh[128];
    sh[t] = v * v;
    __syncthreads();
    for (int s = 64; s > 0; s >>= 1) {
        if (t < s) sh[t] += sh[t + s];
        __syncthreads();
    }
    float n = sqrtf(sh[0]);
    float inv = 1.0f / fmaxf(n, 1e-12f);
    z[(size_t)r * 128 + t] = v * inv;
}

// ---------------- fused cluster head: logits = H[N,64]@Wc2[64,3]+bc2, softmax
__global__ void cluster_kernel(const float* __restrict__ H,
                               const float* __restrict__ Wc2,
                               const float* __restrict__ bc2,
                               float* __restrict__ out, int N) {
    int gtid = blockIdx.x * blockDim.x + threadIdx.x;
    int warp = gtid >> 5;
    int lane = gtid & 31;
    if (warp >= N) return;
    const float* rowp = H + (size_t)warp * 64;
    float d0 = 0.f, d1 = 0.f, d2 = 0.f;
#pragma unroll
    for (int kb = 0; kb < 2; kb++) {
        int k = lane + kb * 32;
        float v = rowp[k];
        d0 = fmaf(v, Wc2[k * 3 + 0], d0);
        d1 = fmaf(v, Wc2[k * 3 + 1], d1);
        d2 = fmaf(v, Wc2[k * 3 + 2], d2);
    }
#pragma unroll
    for (int o = 16; o > 0; o >>= 1) {
        d0 += __shfl_down_sync(0xffffffffu, d0, o);
        d1 += __shfl_down_sync(0xffffffffu, d1, o);
        d2 += __shfl_down_sync(0xffffffffu, d2, o);
    }
    if (lane == 0) {
        d0 += bc2[0]; d1 += bc2[1]; d2 += bc2[2];
        float m = fmaxf(d0, fmaxf(d1, d2));
        float e0 = __expf(d0 - m), e1 = __expf(d1 - m), e2 = __expf(d2 - m);
        float inv = 1.0f / (e0 + e1 + e2);
        out[(size_t)warp * 3 + 0] = e0 * inv;
        out[(size_t)warp * 3 + 1] = e1 * inv;
        out[(size_t)warp * 3 + 2] = e2 * inv;
    }
}

// ---------------- launch -----------------------------------------------------
extern "C" void kernel_launch(void* const* d_in, const int* in_sizes, int n_in,
                              void* d_out, int out_size) {
    const float* x1  = (const float*)d_in[0];
    const int*   ei1 = (const int*)  d_in[1];
    const float* x2  = (const float*)d_in[2];
    const int*   ei2 = (const int*)  d_in[3];
    const float* W1  = (const float*)d_in[4];
    const float* b1  = (const float*)d_in[5];
    const float* W2  = (const float*)d_in[6];
    const float* b2  = (const float*)d_in[7];
    const float* Wp1 = (const float*)d_in[8];
    const float* bp1 = (const float*)d_in[9];
    const float* Wp2 = (const float*)d_in[10];
    const float* bp2 = (const float*)d_in[11];
    const float* Wc1 = (const float*)d_in[12];
    const float* bc1 = (const float*)d_in[13];
    const float* Wc2 = (const float*)d_in[14];
    const float* bc2 = (const float*)d_in[15];

    int N = in_sizes[0] / 128;
    int E = in_sizes[1] / 2;

    float* out    = (float*)d_out;
    float* out_zi = out;
    float* out_zj = out + (size_t)N * 128;
    float* out_ci = out + (size_t)N * 256;
    float* out_cj = out_ci + (size_t)N * 3;

    void *pA, *pB, *pC;
    cudaGetSymbolAddress(&pA, g_bufA);
    cudaGetSymbolAddress(&pB, g_bufB);
    cudaGetSymbolAddress(&pC, g_bufC);
    float* bufA = (float*)pA;
    float* bufB = (float*)pB;
    float* bufC = (float*)pC;

    int gemmGrid = (N + 127) / 128;

    for (int g = 0; g < 2; g++) {
        const float* x  = g ? x2 : x1;
        const int*   ei = g ? ei2 : ei1;
        float* out_z = g ? out_zj : out_zi;
        float* out_c = g ? out_cj : out_ci;

        // build CSR + dinv for this graph
        zero_counts_kernel<<<(N + 255) / 256, 256>>>(N);
        hist_kernel<<<(E + 255) / 256, 256>>>(ei + E, E);
        scan_kernel<<<1, 1024>>>(N);
        fill_csr_kernel<<<(E + 255) / 256, 256>>>(ei, E);

        // GCN layer 1: T1 = (x @ W1) * dinv[row]; agg -> H1 (relu, +b1)
        gemm_kernel<128, 128, 0><<<gemmGrid, 256>>>(x, W1, nullptr, bufA, N);
        agg_kernel<128><<<N, 128>>>(bufA, b1, bufB);

        // GCN layer 2: T2 = (H1 @ W2) * dinv[row]; agg -> Z (relu, +b2)
        gemm_kernel<128, 64, 0><<<gemmGrid, 256>>>(bufB, W2, nullptr, bufA, N);
        agg_kernel<64><<<N, 64>>>(bufA, b2, bufC);

        // instance projector: P = relu(Z@Wp1+bp1); U = P@Wp2+bp2 -> l2norm
        gemm_kernel<64, 64, 1><<<gemmGrid, 256>>>(bufC, Wp1, bp1, bufA, N);
        gemm_kernel<64, 128, 2><<<gemmGrid, 256>>>(bufA, Wp2, bp2, out_z, N);
        l2norm_kernel<<<N, 128>>>(out_z);

        // cluster projector: Hc = relu(Z@Wc1+bc1); softmax(Hc@Wc2+bc2)
        gemm_kernel<64, 64, 1><<<gemmGrid, 256>>>(bufC, Wc1, bc1, bufB, N);
        cluster_kernel<<<((N * 32) + 255) / 256, 256>>>(bufB, Wc2, bc2, out_c, N);
    }
}

// round 2
// speedup vs baseline: 1.3343x; 1.3343x over previous
#include <cuda_runtime.h>
#include <math.h>

// Problem constants (shapes fixed by the dataset)
#define NMAX 50000
#define EMAX 800000

// ---------------- scratch (static device globals; no allocation) ------------
__device__ float g_bufA[NMAX * 128];   // GEMM outputs / pre-agg features
__device__ float g_bufB[NMAX * 128];   // post-agg hidden / cluster hidden
__device__ float g_bufC[NMAX * 64];    // encoder output Z
__device__ float g_dinv[NMAX];         // 1/sqrt(deg) (deg includes self loop)
__device__ int   g_deg[NMAX];
__device__ int   g_off[NMAX + 1];
__device__ int   g_cur[NMAX];
__device__ int   g_csr[EMAX];

// ---------------- graph preprocessing ---------------------------------------
__global__ void zero_counts_kernel(int n) {
    int i = blockIdx.x * blockDim.x + threadIdx.x;
    if (i < n) { g_deg[i] = 0; g_cur[i] = 0; }
}

__global__ void hist_kernel(const int* __restrict__ col, int E) {
    int i = blockIdx.x * blockDim.x + threadIdx.x;
    if (i < E) atomicAdd(&g_deg[col[i]], 1);
}

// exclusive scan of g_deg -> g_off, plus dinv = rsqrt(deg+1). One block.
__global__ void scan_kernel(int n) {
    __shared__ int sh[1024];
    __shared__ int carry;
    int tid = threadIdx.x;
    if (tid == 0) carry = 0;
    __syncthreads();
    for (int base = 0; base < n; base += 1024) {
        int i = base + tid;
        int v = (i < n) ? g_deg[i] : 0;
        sh[tid] = v;
        __syncthreads();
        for (int d = 1; d < 1024; d <<= 1) {
            int t = (tid >= d) ? sh[tid - d] : 0;
            __syncthreads();
            sh[tid] += t;
            __syncthreads();
        }
        if (i < n) {
            g_off[i]  = carry + sh[tid] - v;
            g_dinv[i] = rsqrtf((float)(v + 1));
        }
        __syncthreads();
        if (tid == 0) carry += sh[1023];
        __syncthreads();
    }
    if (tid == 0) g_off[n] = carry;
}

__global__ void fill_csr_kernel(const int* __restrict__ ei, int E) {
    int i = blockIdx.x * blockDim.x + threadIdx.x;
    if (i < E) {
        int r = ei[i];       // source (x_j)
        int c = ei[E + i];   // target
        int p = atomicAdd(&g_cur[c], 1);
        g_csr[g_off[c] + p] = r;
    }
}

// ---------------- neighbor aggregation ---------------------------------------
// out[node] = relu( dinv[node] * (G[node] + sum_{nbr in csr(node)} G[nbr]) + bias )
// (G rows are already pre-scaled by dinv[source])
template <int F>
__global__ void agg_kernel(const float* __restrict__ G,
                           const float* __restrict__ bias,
                           float* __restrict__ out) {
    int node = blockIdx.x;
    int f = threadIdx.x;
    __shared__ int nb[F];
    int s = g_off[node], e = g_off[node + 1];
    float acc = G[(size_t)node * F + f];
    for (int j0 = s; j0 < e; j0 += F) {
        int cnt = min(F, e - j0);
        if (f < cnt) nb[f] = g_csr[j0 + f];
        __syncthreads();
        int t = 0;
        for (; t + 4 <= cnt; t += 4) {
            float v0 = G[(size_t)nb[t]     * F + f];
            float v1 = G[(size_t)nb[t + 1] * F + f];
            float v2 = G[(size_t)nb[t + 2] * F + f];
            float v3 = G[(size_t)nb[t + 3] * F + f];
            acc += v0; acc += v1; acc += v2; acc += v3;
        }
        for (; t < cnt; t++) acc += G[(size_t)nb[t] * F + f];
        __syncthreads();
    }
    float v = g_dinv[node] * acc + bias[f];
    out[(size_t)node * F + f] = fmaxf(v, 0.0f);
}

// ---------------- TF32 tensor-core GEMM --------------------------------------
// C[N,F] = A[N,K] @ B[K,F], tf32 inputs (rna-rounded), fp32 accumulate.
// EPI 0: out = acc * g_dinv[row]
// EPI 1: out = relu(acc + vec[col])
// EPI 2: out = acc + vec[col]

__device__ __forceinline__ unsigned f2tf32(float x) {
    unsigned r;
    asm("cvt.rna.tf32.f32 %0, %1;" : "=r"(r) : "f"(x));
    return r;
}

__device__ __forceinline__ void mma_tf32(float c[4], const unsigned a[4],
                                         const unsigned b[2]) {
    asm volatile(
        "mma.sync.aligned.m16n8k8.row.col.f32.tf32.tf32.f32 "
        "{%0,%1,%2,%3}, {%4,%5,%6,%7}, {%8,%9}, {%0,%1,%2,%3};"
        : "+f"(c[0]), "+f"(c[1]), "+f"(c[2]), "+f"(c[3])
        : "r"(a[0]), "r"(a[1]), "r"(a[2]), "r"(a[3]), "r"(b[0]), "r"(b[1]));
}

template <int K, int F, int EPI>
__global__ void gemm_tc(const float* __restrict__ A, const float* __restrict__ B,
                        const float* __restrict__ vec, float* __restrict__ C,
                        int N) {
    constexpr int BK = 32;
    constexpr int WN = F / 32;           // warps along N (warp tile 64x32)
    constexpr int THREADS = 32 * 2 * WN; // 2 warps along M
    __shared__ unsigned As[128][36];     // [m][k], stride 36 -> conflict-free frags
    __shared__ unsigned Bs[F][36];       // [n][k] (transposed), stride 36

    int tid = threadIdx.x;
    int lane = tid & 31;
    int warp = tid >> 5;
    int warpM = warp / WN;
    int warpN = warp % WN;
    int rowBase = blockIdx.x * 128;

    float acc[4][4][4];
#pragma unroll
    for (int i = 0; i < 4; i++)
#pragma unroll
        for (int j = 0; j < 4; j++)
#pragma unroll
            for (int q = 0; q < 4; q++) acc[i][j][q] = 0.0f;

    for (int kc = 0; kc < K; kc += BK) {
        // Load A tile (128 x BK) as float4, convert to tf32 bits
        constexpr int AQ = (128 * BK / 4) / THREADS;
#pragma unroll
        for (int q = 0; q < AQ; q++) {
            int lin = tid + q * THREADS;   // 0..1023
            int r = lin >> 3;
            int k4 = lin & 7;
            float4 v = make_float4(0.f, 0.f, 0.f, 0.f);
            int gr = rowBase + r;
            if (gr < N)
                v = *reinterpret_cast<const float4*>(&A[(size_t)gr * K + kc + k4 * 4]);
            uint4 t;
            t.x = f2tf32(v.x); t.y = f2tf32(v.y);
            t.z = f2tf32(v.z); t.w = f2tf32(v.w);
            *reinterpret_cast<uint4*>(&As[r][k4 * 4]) = t;
        }
        // Load B tile (BK x F) transposed into Bs[n][k]
        {
            int n = tid % F;
            int kg = tid / F;                       // 0..THREADS/F-1
            constexpr int KPER = BK / (THREADS / F);
#pragma unroll
            for (int q = 0; q < KPER; q++) {
                int kk = kg * KPER + q;
                Bs[n][kk] = f2tf32(B[(size_t)(kc + kk) * F + n]);
            }
        }
        __syncthreads();

#pragma unroll
        for (int ks = 0; ks < BK / 8; ks++) {
            int kA = ks * 8 + (lane & 3);
            unsigned a[4][4], b[4][2];
            int r0 = warpM * 64 + (lane >> 2);
#pragma unroll
            for (int mf = 0; mf < 4; mf++) {
                int rr = r0 + mf * 16;
                a[mf][0] = As[rr][kA];
                a[mf][1] = As[rr + 8][kA];
                a[mf][2] = As[rr][kA + 4];
                a[mf][3] = As[rr + 8][kA + 4];
            }
            int c0 = warpN * 32 + (lane >> 2);
#pragma unroll
            for (int nf = 0; nf < 4; nf++) {
                b[nf][0] = Bs[c0 + nf * 8][kA];
                b[nf][1] = Bs[c0 + nf * 8][kA + 4];
            }
#pragma unroll
            for (int mf = 0; mf < 4; mf++)
#pragma unroll
                for (int nf = 0; nf < 4; nf++) mma_tf32(acc[mf][nf], a[mf], b[nf]);
        }
        __syncthreads();
    }

    // Epilogue: each thread owns 2x2 float2 blocks per fragment
    int rThr = rowBase + warpM * 64 + (lane >> 2);
    int cThr = warpN * 32 + (lane & 3) * 2;
#pragma unroll
    for (int mf = 0; mf < 4; mf++) {
#pragma unroll
        for (int half = 0; half < 2; half++) {
            int gr = rThr + mf * 16 + half * 8;
            if (gr >= N) continue;
            float rs = (EPI == 0) ? g_dinv[gr] : 1.0f;
#pragma unroll
            for (int nf = 0; nf < 4; nf++) {
                int gc = cThr + nf * 8;
                float v0 = acc[mf][nf][half * 2 + 0];
                float v1 = acc[mf][nf][half * 2 + 1];
                if (EPI == 0) { v0 *= rs; v1 *= rs; }
                else {
                    v0 += vec[gc]; v1 += vec[gc + 1];
                    if (EPI == 1) { v0 = fmaxf(v0, 0.f); v1 = fmaxf(v1, 0.f); }
                }
                *reinterpret_cast<float2*>(&C[(size_t)gr * F + gc]) =
                    make_float2(v0, v1);
            }
        }
    }
}

// ---------------- L2 normalize rows of length 128 (in place) -----------------
__global__ void l2norm_kernel(float* __restrict__ z) {
    int r = blockIdx.x;
    int t = threadIdx.x;   // 128
    float v = z[(size_t)r * 128 + t];
    __shared__ float sh[128];
    sh[t] = v * v;
    __syncthreads();
    for (int s = 64; s > 0; s >>= 1) {
        if (t < s) sh[t] += sh[t + s];
        __syncthreads();
    }
    float n = sqrtf(sh[0]);
    float inv = 1.0f / fmaxf(n, 1e-12f);
    z[(size_t)r * 128 + t] = v * inv;
}

// ---------------- fused cluster head: logits = H[N,64]@Wc2[64,3]+bc2, softmax
__global__ void cluster_kernel(const float* __restrict__ H,
                               const float* __restrict__ Wc2,
                               const float* __restrict__ bc2,
                               float* __restrict__ out, int N) {
    int gtid = blockIdx.x * blockDim.x + threadIdx.x;
    int warp = gtid >> 5;
    int lane = gtid & 31;
    if (warp >= N) return;
    const float* rowp = H + (size_t)warp * 64;
    float d0 = 0.f, d1 = 0.f, d2 = 0.f;
#pragma unroll
    for (int kb = 0; kb < 2; kb++) {
        int k = lane + kb * 32;
        float v = rowp[k];
        d0 = fmaf(v, Wc2[k * 3 + 0], d0);
        d1 = fmaf(v, Wc2[k * 3 + 1], d1);
        d2 = fmaf(v, Wc2[k * 3 + 2], d2);
    }
#pragma unroll
    for (int o = 16; o > 0; o >>= 1) {
        d0 += __shfl_down_sync(0xffffffffu, d0, o);
        d1 += __shfl_down_sync(0xffffffffu, d1, o);
        d2 += __shfl_down_sync(0xffffffffu, d2, o);
    }
    if (lane == 0) {
        d0 += bc2[0]; d1 += bc2[1]; d2 += bc2[2];
        float m = fmaxf(d0, fmaxf(d1, d2));
        float e0 = __expf(d0 - m), e1 = __expf(d1 - m), e2 = __expf(d2 - m);
        float inv = 1.0f / (e0 + e1 + e2);
        out[(size_t)warp * 3 + 0] = e0 * inv;
        out[(size_t)warp * 3 + 1] = e1 * inv;
        out[(size_t)warp * 3 + 2] = e2 * inv;
    }
}

// ---------------- launch -----------------------------------------------------
extern "C" void kernel_launch(void* const* d_in, const int* in_sizes, int n_in,
                              void* d_out, int out_size) {
    const float* x1  = (const float*)d_in[0];
    const int*   ei1 = (const int*)  d_in[1];
    const float* x2  = (const float*)d_in[2];
    const int*   ei2 = (const int*)  d_in[3];
    const float* W1  = (const float*)d_in[4];
    const float* b1  = (const float*)d_in[5];
    const float* W2  = (const float*)d_in[6];
    const float* b2  = (const float*)d_in[7];
    const float* Wp1 = (const float*)d_in[8];
    const float* bp1 = (const float*)d_in[9];
    const float* Wp2 = (const float*)d_in[10];
    const float* bp2 = (const float*)d_in[11];
    const float* Wc1 = (const float*)d_in[12];
    const float* bc1 = (const float*)d_in[13];
    const float* Wc2 = (const float*)d_in[14];
    const float* bc2 = (const float*)d_in[15];

    int N = in_sizes[0] / 128;
    int E = in_sizes[1] / 2;

    float* out    = (float*)d_out;
    float* out_zi = out;
    float* out_zj = out + (size_t)N * 128;
    float* out_ci = out + (size_t)N * 256;
    float* out_cj = out_ci + (size_t)N * 3;

    void *pA, *pB, *pC;
    cudaGetSymbolAddress(&pA, g_bufA);
    cudaGetSymbolAddress(&pB, g_bufB);
    cudaGetSymbolAddress(&pC, g_bufC);
    float* bufA = (float*)pA;
    float* bufB = (float*)pB;
    float* bufC = (float*)pC;

    int gemmGrid = (N + 127) / 128;

    for (int g = 0; g < 2; g++) {
        const float* x  = g ? x2 : x1;
        const int*   ei = g ? ei2 : ei1;
        float* out_z = g ? out_zj : out_zi;
        float* out_c = g ? out_cj : out_ci;

        // build CSR + dinv for this graph
        zero_counts_kernel<<<(N + 255) / 256, 256>>>(N);
        hist_kernel<<<(E + 255) / 256, 256>>>(ei + E, E);
        scan_kernel<<<1, 1024>>>(N);
        fill_csr_kernel<<<(E + 255) / 256, 256>>>(ei, E);

        // GCN layer 1: T1 = (x @ W1) * dinv[row]; agg -> H1 (relu, +b1)
        gemm_tc<128, 128, 0><<<gemmGrid, 256>>>(x, W1, nullptr, bufA, N);
        agg_kernel<128><<<N, 128>>>(bufA, b1, bufB);

        // GCN layer 2: T2 = (H1 @ W2) * dinv[row]; agg -> Z (relu, +b2)
        gemm_tc<128, 64, 0><<<gemmGrid, 128>>>(bufB, W2, nullptr, bufA, N);
        agg_kernel<64><<<N, 64>>>(bufA, b2, bufC);

        // instance projector: P = relu(Z@Wp1+bp1); U = P@Wp2+bp2 -> l2norm
        gemm_tc<64, 64, 1><<<gemmGrid, 128>>>(bufC, Wp1, bp1, bufA, N);
        gemm_tc<64, 128, 2><<<gemmGrid, 256>>>(bufA, Wp2, bp2, out_z, N);
        l2norm_kernel<<<N, 128>>>(out_z);

        // cluster projector: Hc = relu(Z@Wc1+bc1); softmax(Hc@Wc2+bc2)
        gemm_tc<64, 64, 1><<<gemmGrid, 128>>>(bufC, Wc1, bc1, bufB, N);
        cluster_kernel<<<((N * 32) + 255) / 256, 256>>>(bufB, Wc2, bc2, out_c, N);
    }
}

// round 3
// speedup vs baseline: 2.2518x; 1.6877x over previous
#include <cuda_runtime.h>
#include <math.h>

#define NMAX 50000
#define EMAX 800000

// ---------------- scratch (static device globals; no allocation) ------------
__device__ float g_bufA[NMAX * 128];
__device__ float g_bufB[NMAX * 128];
__device__ float g_bufC[NMAX * 64];
__device__ float g_dinv[NMAX];
__device__ int   g_deg[NMAX];
__device__ int   g_off[NMAX + 1];
__device__ int   g_cur[NMAX];
__device__ int   g_csr[EMAX];
__device__ int   g_bsum[64];
__device__ int   g_bpre[64];
__device__ float g_wcomb[64 * 128];   // [Wp1 | Wc1]
__device__ float g_bcomb[128];        // [bp1 | bc1]

// ---------------- weight concat (once per call) ------------------------------
__global__ void combine_wb(const float* __restrict__ Wp1, const float* __restrict__ Wc1,
                           const float* __restrict__ bp1, const float* __restrict__ bc1) {
    int i = blockIdx.x * blockDim.x + threadIdx.x;
    if (i < 64 * 128) {
        int k = i >> 7, n = i & 127;
        g_wcomb[i] = (n < 64) ? Wp1[k * 64 + n] : Wc1[k * 64 + n - 64];
    }
    if (i < 128) g_bcomb[i] = (i < 64) ? bp1[i] : bc1[i - 64];
}

// ---------------- graph preprocessing ---------------------------------------
__global__ void zero_deg_kernel(int n) {
    int i = blockIdx.x * blockDim.x + threadIdx.x;
    if (i < n) g_deg[i] = 0;
}

__global__ void hist_kernel(const int* __restrict__ col, int E) {
    int i = blockIdx.x * blockDim.x + threadIdx.x;
    if (i < E) atomicAdd(&g_deg[col[i]], 1);
}

// Phase A: per-1024-block exclusive scan of g_deg -> g_off (local), totals -> g_bsum
__global__ void scan_blocks_kernel(int n) {
    int b = blockIdx.x, tid = threadIdx.x;
    int i = b * 1024 + tid;
    int lane = tid & 31, w = tid >> 5;
    int v = (i < n) ? g_deg[i] : 0;
    int s = v;
#pragma unroll
    for (int o = 1; o < 32; o <<= 1) {
        int t = __shfl_up_sync(0xffffffffu, s, o);
        if (lane >= o) s += t;
    }
    __shared__ int wsum[32];
    if (lane == 31) wsum[w] = s;
    __syncthreads();
    if (w == 0) {
        int t = wsum[lane];
#pragma unroll
        for (int o = 1; o < 32; o <<= 1) {
            int u = __shfl_up_sync(0xffffffffu, t, o);
            if (lane >= o) t += u;
        }
        wsum[lane] = t;
    }
    __syncthreads();
    int excl = s - v + (w > 0 ? wsum[w - 1] : 0);
    if (i < n) {
        g_off[i] = excl;
        g_dinv[i] = rsqrtf((float)(v + 1));
    }
    if (tid == 0) g_bsum[b] = wsum[31];
}

// Phase B: scan block totals (nb <= 64), write grand total to g_off[n]
__global__ void scan_top_kernel(int nb, int n) {
    int tid = threadIdx.x;   // 64
    __shared__ int sh[64];
    int v = (tid < nb) ? g_bsum[tid] : 0;
    sh[tid] = v;
    __syncthreads();
#pragma unroll
    for (int d = 1; d < 64; d <<= 1) {
        int t = (tid >= d) ? sh[tid - d] : 0;
        __syncthreads();
        sh[tid] += t;
        __syncthreads();
    }
    if (tid < nb) g_bpre[tid] = sh[tid] - v;
    if (tid == 63) g_off[n] = sh[63];
}

// Phase C: add block prefixes, zero cursors
__global__ void scan_add_kernel(int n) {
    int i = blockIdx.x * blockDim.x + threadIdx.x;
    if (i < n) {
        g_off[i] += g_bpre[i >> 10];
        g_cur[i] = 0;
    }
}

__global__ void fill_csr_kernel(const int* __restrict__ ei, int E) {
    int i = blockIdx.x * blockDim.x + threadIdx.x;
    if (i < E) {
        int r = ei[i];
        int c = ei[E + i];
        int p = atomicAdd(&g_cur[c], 1);
        g_csr[g_off[c] + p] = r;
    }
}

// ---------------- neighbor aggregation: warp per node, vector rows ------------
// out[node] = relu( dinv[node] * (G[node] + sum_nbr G[nbr]) + bias )
template <int F>
__global__ void agg_warp_kernel(const float* __restrict__ G,
                                const float* __restrict__ bias,
                                float* __restrict__ out, int N) {
    constexpr int VEC = F / 32;   // 4 or 2 floats per lane
    int node = blockIdx.x * (blockDim.x >> 5) + (threadIdx.x >> 5);
    if (node >= N) return;
    int lane = threadIdx.x & 31;
    int s = g_off[node], e = g_off[node + 1];

    if constexpr (VEC == 4) {
        float4 acc = *reinterpret_cast<const float4*>(&G[(size_t)node * F + lane * 4]);
        int j = s;
        for (; j + 4 <= e; j += 4) {
            int n0 = g_csr[j], n1 = g_csr[j + 1], n2 = g_csr[j + 2], n3 = g_csr[j + 3];
            float4 v0 = *reinterpret_cast<const float4*>(&G[(size_t)n0 * F + lane * 4]);
            float4 v1 = *reinterpret_cast<const float4*>(&G[(size_t)n1 * F + lane * 4]);
            float4 v2 = *reinterpret_cast<const float4*>(&G[(size_t)n2 * F + lane * 4]);
            float4 v3 = *reinterpret_cast<const float4*>(&G[(size_t)n3 * F + lane * 4]);
            acc.x += v0.x + v1.x + v2.x + v3.x;
            acc.y += v0.y + v1.y + v2.y + v3.y;
            acc.z += v0.z + v1.z + v2.z + v3.z;
            acc.w += v0.w + v1.w + v2.w + v3.w;
        }
        for (; j < e; j++) {
            float4 v = *reinterpret_cast<const float4*>(&G[(size_t)g_csr[j] * F + lane * 4]);
            acc.x += v.x; acc.y += v.y; acc.z += v.z; acc.w += v.w;
        }
        float d = g_dinv[node];
        float4 bb = *reinterpret_cast<const float4*>(&bias[lane * 4]);
        float4 o;
        o.x = fmaxf(fmaf(d, acc.x, bb.x), 0.f);
        o.y = fmaxf(fmaf(d, acc.y, bb.y), 0.f);
        o.z = fmaxf(fmaf(d, acc.z, bb.z), 0.f);
        o.w = fmaxf(fmaf(d, acc.w, bb.w), 0.f);
        *reinterpret_cast<float4*>(&out[(size_t)node * F + lane * 4]) = o;
    } else {
        float2 acc = *reinterpret_cast<const float2*>(&G[(size_t)node * F + lane * 2]);
        int j = s;
        for (; j + 4 <= e; j += 4) {
            int n0 = g_csr[j], n1 = g_csr[j + 1], n2 = g_csr[j + 2], n3 = g_csr[j + 3];
            float2 v0 = *reinterpret_cast<const float2*>(&G[(size_t)n0 * F + lane * 2]);
            float2 v1 = *reinterpret_cast<const float2*>(&G[(size_t)n1 * F + lane * 2]);
            float2 v2 = *reinterpret_cast<const float2*>(&G[(size_t)n2 * F + lane * 2]);
            float2 v3 = *reinterpret_cast<const float2*>(&G[(size_t)n3 * F + lane * 2]);
            acc.x += v0.x + v1.x + v2.x + v3.x;
            acc.y += v0.y + v1.y + v2.y + v3.y;
        }
        for (; j < e; j++) {
            float2 v = *reinterpret_cast<const float2*>(&G[(size_t)g_csr[j] * F + lane * 2]);
            acc.x += v.x; acc.y += v.y;
        }
        float d = g_dinv[node];
        float2 bb = *reinterpret_cast<const float2*>(&bias[lane * 2]);
        float2 o;
        o.x = fmaxf(fmaf(d, acc.x, bb.x), 0.f);
        o.y = fmaxf(fmaf(d, acc.y, bb.y), 0.f);
        *reinterpret_cast<float2*>(&out[(size_t)node * F + lane * 2]) = o;
    }
}

// ---------------- TF32 tensor-core GEMM --------------------------------------
// C[N,F] = A[N,K(lda=LDA)] @ B[K,F], tf32 inputs (rna), fp32 accumulate.
// EPI 0: out = acc * g_dinv[row]
// EPI 1: out = relu(acc + vec[col])
// EPI 2: out = acc + vec[col]
// EPI 3: out = l2norm_row(acc + vec[col])   (requires F==128 == full row)

__device__ __forceinline__ unsigned f2tf32(float x) {
    unsigned r;
    asm("cvt.rna.tf32.f32 %0, %1;" : "=r"(r) : "f"(x));
    return r;
}

__device__ __forceinline__ void mma_tf32(float c[4], const unsigned a[4],
                                         const unsigned b[2]) {
    asm volatile(
        "mma.sync.aligned.m16n8k8.row.col.f32.tf32.tf32.f32 "
        "{%0,%1,%2,%3}, {%4,%5,%6,%7}, {%8,%9}, {%0,%1,%2,%3};"
        : "+f"(c[0]), "+f"(c[1]), "+f"(c[2]), "+f"(c[3])
        : "r"(a[0]), "r"(a[1]), "r"(a[2]), "r"(a[3]), "r"(b[0]), "r"(b[1]));
}

template <int K, int F, int EPI, int LDA>
__global__ void gemm_tc(const float* __restrict__ A, const float* __restrict__ B,
                        const float* __restrict__ vec, float* __restrict__ C,
                        int N) {
    constexpr int BK = 32;
    constexpr int WN = F / 32;
    constexpr int THREADS = 32 * 2 * WN;
    __shared__ unsigned As[128][36];
    __shared__ unsigned Bs[F][36];

    int tid = threadIdx.x;
    int lane = tid & 31;
    int warp = tid >> 5;
    int warpM = warp / WN;
    int warpN = warp % WN;
    int rowBase = blockIdx.x * 128;

    float acc[4][4][4];
#pragma unroll
    for (int i = 0; i < 4; i++)
#pragma unroll
        for (int j = 0; j < 4; j++)
#pragma unroll
            for (int q = 0; q < 4; q++) acc[i][j][q] = 0.0f;

    for (int kc = 0; kc < K; kc += BK) {
        constexpr int AQ = (128 * BK / 4) / THREADS;
#pragma unroll
        for (int q = 0; q < AQ; q++) {
            int lin = tid + q * THREADS;
            int r = lin >> 3;
            int k4 = lin & 7;
            float4 v = make_float4(0.f, 0.f, 0.f, 0.f);
            int gr = rowBase + r;
            if (gr < N)
                v = *reinterpret_cast<const float4*>(&A[(size_t)gr * LDA + kc + k4 * 4]);
            uint4 t;
            t.x = f2tf32(v.x); t.y = f2tf32(v.y);
            t.z = f2tf32(v.z); t.w = f2tf32(v.w);
            *reinterpret_cast<uint4*>(&As[r][k4 * 4]) = t;
        }
        {
            int n = tid % F;
            int kg = tid / F;
            constexpr int KPER = BK / (THREADS / F);
#pragma unroll
            for (int q = 0; q < KPER; q++) {
                int kk = kg * KPER + q;
                Bs[n][kk] = f2tf32(B[(size_t)(kc + kk) * F + n]);
            }
        }
        __syncthreads();

#pragma unroll
        for (int ks = 0; ks < BK / 8; ks++) {
            int kA = ks * 8 + (lane & 3);
            unsigned a[4][4], b[4][2];
            int r0 = warpM * 64 + (lane >> 2);
#pragma unroll
            for (int mf = 0; mf < 4; mf++) {
                int rr = r0 + mf * 16;
                a[mf][0] = As[rr][kA];
                a[mf][1] = As[rr + 8][kA];
                a[mf][2] = As[rr][kA + 4];
                a[mf][3] = As[rr + 8][kA + 4];
            }
            int c0 = warpN * 32 + (lane >> 2);
#pragma unroll
            for (int nf = 0; nf < 4; nf++) {
                b[nf][0] = Bs[c0 + nf * 8][kA];
                b[nf][1] = Bs[c0 + nf * 8][kA + 4];
            }
#pragma unroll
            for (int mf = 0; mf < 4; mf++)
#pragma unroll
                for (int nf = 0; nf < 4; nf++) mma_tf32(acc[mf][nf], a[mf], b[nf]);
        }
        __syncthreads();
    }

    int rThr = rowBase + warpM * 64 + (lane >> 2);
    int cThr = warpN * 32 + (lane & 3) * 2;

    if constexpr (EPI == 3) {
        // bias + row L2 norm (F == 128 covers the whole row in this block)
        __shared__ float ss[128];
        if (tid < 128) ss[tid] = 0.f;
        __syncthreads();
#pragma unroll
        for (int mf = 0; mf < 4; mf++) {
#pragma unroll
            for (int half = 0; half < 2; half++) {
                int lr = warpM * 64 + mf * 16 + half * 8 + (lane >> 2);
                float q = 0.f;
#pragma unroll
                for (int nf = 0; nf < 4; nf++) {
                    int gc = cThr + nf * 8;
                    float v0 = acc[mf][nf][half * 2 + 0] + vec[gc];
                    float v1 = acc[mf][nf][half * 2 + 1] + vec[gc + 1];
                    acc[mf][nf][half * 2 + 0] = v0;
                    acc[mf][nf][half * 2 + 1] = v1;
                    q = fmaf(v0, v0, q);
                    q = fmaf(v1, v1, q);
                }
                atomicAdd(&ss[lr], q);
            }
        }
        __syncthreads();
#pragma unroll
        for (int mf = 0; mf < 4; mf++) {
#pragma unroll
            for (int half = 0; half < 2; half++) {
                int lr = warpM * 64 + mf * 16 + half * 8 + (lane >> 2);
                int gr = rowBase + lr;
                if (gr >= N) continue;
                float nrm = sqrtf(ss[lr]);
                float inv = 1.0f / fmaxf(nrm, 1e-12f);
#pragma unroll
                for (int nf = 0; nf < 4; nf++) {
                    int gc = cThr + nf * 8;
                    *reinterpret_cast<float2*>(&C[(size_t)gr * F + gc]) =
                        make_float2(acc[mf][nf][half * 2 + 0] * inv,
                                    acc[mf][nf][half * 2 + 1] * inv);
                }
            }
        }
    } else {
#pragma unroll
        for (int mf = 0; mf < 4; mf++) {
#pragma unroll
            for (int half = 0; half < 2; half++) {
                int gr = rThr + mf * 16 + half * 8;
                if (gr >= N) continue;
                float rs = (EPI == 0) ? g_dinv[gr] : 1.0f;
#pragma unroll
                for (int nf = 0; nf < 4; nf++) {
                    int gc = cThr + nf * 8;
                    float v0 = acc[mf][nf][half * 2 + 0];
                    float v1 = acc[mf][nf][half * 2 + 1];
                    if (EPI == 0) { v0 *= rs; v1 *= rs; }
                    else {
                        v0 += vec[gc]; v1 += vec[gc + 1];
                        if (EPI == 1) { v0 = fmaxf(v0, 0.f); v1 = fmaxf(v1, 0.f); }
                    }
                    *reinterpret_cast<float2*>(&C[(size_t)gr * F + gc]) =
                        make_float2(v0, v1);
                }
            }
        }
    }
}

// ---------------- fused cluster head: softmax((Hc@Wc2)+bc2) ------------------
// Hc rows live at H + node*128 + 64 (64 contiguous floats)
__global__ void cluster_kernel(const float* __restrict__ H,
                               const float* __restrict__ Wc2,
                               const float* __restrict__ bc2,
                               float* __restrict__ out, int N) {
    int gtid = blockIdx.x * blockDim.x + threadIdx.x;
    int node = gtid >> 5;
    int lane = gtid & 31;
    if (node >= N) return;
    const float* rowp = H + (size_t)node * 128 + 64;
    float d0 = 0.f, d1 = 0.f, d2 = 0.f;
#pragma unroll
    for (int kb = 0; kb < 2; kb++) {
        int k = lane + kb * 32;
        float v = rowp[k];
        d0 = fmaf(v, Wc2[k * 3 + 0], d0);
        d1 = fmaf(v, Wc2[k * 3 + 1], d1);
        d2 = fmaf(v, Wc2[k * 3 + 2], d2);
    }
#pragma unroll
    for (int o = 16; o > 0; o >>= 1) {
        d0 += __shfl_down_sync(0xffffffffu, d0, o);
        d1 += __shfl_down_sync(0xffffffffu, d1, o);
        d2 += __shfl_down_sync(0xffffffffu, d2, o);
    }
    if (lane == 0) {
        d0 += bc2[0]; d1 += bc2[1]; d2 += bc2[2];
        float m = fmaxf(d0, fmaxf(d1, d2));
        float e0 = __expf(d0 - m), e1 = __expf(d1 - m), e2 = __expf(d2 - m);
        float inv = 1.0f / (e0 + e1 + e2);
        out[(size_t)node * 3 + 0] = e0 * inv;
        out[(size_t)node * 3 + 1] = e1 * inv;
        out[(size_t)node * 3 + 2] = e2 * inv;
    }
}

// ---------------- launch -----------------------------------------------------
extern "C" void kernel_launch(void* const* d_in, const int* in_sizes, int n_in,
                              void* d_out, int out_size) {
    const float* x1  = (const float*)d_in[0];
    const int*   ei1 = (const int*)  d_in[1];
    const float* x2  = (const float*)d_in[2];
    const int*   ei2 = (const int*)  d_in[3];
    const float* W1  = (const float*)d_in[4];
    const float* b1  = (const float*)d_in[5];
    const float* W2  = (const float*)d_in[6];
    const float* b2  = (const float*)d_in[7];
    const float* Wp1 = (const float*)d_in[8];
    const float* bp1 = (const float*)d_in[9];
    const float* Wp2 = (const float*)d_in[10];
    const float* bp2 = (const float*)d_in[11];
    const float* Wc1 = (const float*)d_in[12];
    const float* bc1 = (const float*)d_in[13];
    const float* Wc2 = (const float*)d_in[14];
    const float* bc2 = (const float*)d_in[15];

    int N = in_sizes[0] / 128;
    int E = in_sizes[1] / 2;

    float* out    = (float*)d_out;
    float* out_zi = out;
    float* out_zj = out + (size_t)N * 128;
    float* out_ci = out + (size_t)N * 256;
    float* out_cj = out_ci + (size_t)N * 3;

    void *pA, *pB, *pC, *pW, *pBi;
    cudaGetSymbolAddress(&pA, g_bufA);
    cudaGetSymbolAddress(&pB, g_bufB);
    cudaGetSymbolAddress(&pC, g_bufC);
    cudaGetSymbolAddress(&pW, g_wcomb);
    cudaGetSymbolAddress(&pBi, g_bcomb);
    float* bufA = (float*)pA;
    float* bufB = (float*)pB;
    float* bufC = (float*)pC;
    float* wcomb = (float*)pW;
    float* bcomb = (float*)pBi;

    int gemmGrid = (N + 127) / 128;
    int scanBlocks = (N + 1023) / 1024;

    combine_wb<<<(64 * 128 + 255) / 256, 256>>>(Wp1, Wc1, bp1, bc1);

    for (int g = 0; g < 2; g++) {
        const float* x  = g ? x2 : x1;
        const int*   ei = g ? ei2 : ei1;
        float* out_z = g ? out_zj : out_zi;
        float* out_c = g ? out_cj : out_ci;

        // CSR + dinv
        zero_deg_kernel<<<(N + 255) / 256, 256>>>(N);
        hist_kernel<<<(E + 255) / 256, 256>>>(ei + E, E);
        scan_blocks_kernel<<<scanBlocks, 1024>>>(N);
        scan_top_kernel<<<1, 64>>>(scanBlocks, N);
        scan_add_kernel<<<(N + 255) / 256, 256>>>(N);
        fill_csr_kernel<<<(E + 255) / 256, 256>>>(ei, E);

        // GCN layer 1
        gemm_tc<128, 128, 0, 128><<<gemmGrid, 256>>>(x, W1, nullptr, bufA, N);
        agg_warp_kernel<128><<<(N + 7) / 8, 256>>>(bufA, b1, bufB, N);

        // GCN layer 2
        gemm_tc<128, 64, 0, 128><<<gemmGrid, 128>>>(bufB, W2, nullptr, bufA, N);
        agg_warp_kernel<64><<<(N + 7) / 8, 256>>>(bufA, b2, bufC, N);

        // combined projector: [P | Hc] = relu(Z @ [Wp1|Wc1] + [bp1|bc1])
        gemm_tc<64, 128, 1, 64><<<gemmGrid, 256>>>(bufC, wcomb, bcomb, bufB, N);

        // instance head: l2norm(P @ Wp2 + bp2), fused in epilogue
        gemm_tc<64, 128, 3, 128><<<gemmGrid, 256>>>(bufB, Wp2, bp2, out_z, N);

        // cluster head: softmax(Hc @ Wc2 + bc2)
        cluster_kernel<<<((N * 32) + 255) / 256, 256>>>(bufB, Wc2, bc2, out_c, N);
    }
}

// round 5
// speedup vs baseline: 2.5609x; 1.1373x over previous
#include <cuda_runtime.h>
#include <math.h>

#define NMAX 50000
#define EMAX 800000
#define N2MAX (2 * NMAX)
#define E2MAX (2 * EMAX)

// ---------------- scratch (static device globals; no allocation) ------------
__device__ float g_bufA[N2MAX * 128];
__device__ float g_bufB[N2MAX * 128];
__device__ float g_bufC[N2MAX * 64];
__device__ float g_dinv[N2MAX];
__device__ int   g_deg[N2MAX];
__device__ int   g_off[N2MAX + 1];
__device__ int   g_cur[N2MAX];
__device__ int   g_csr[E2MAX];
__device__ int   g_bsum[128];
__device__ int   g_bpre[128];
__device__ float g_wcomb[64 * 128];   // [Wp1 | Wc1]
__device__ float g_bcomb[128];        // [bp1 | bc1]

// ---------------- weight concat (once per call) ------------------------------
__global__ void combine_wb(const float* __restrict__ Wp1, const float* __restrict__ Wc1,
                           const float* __restrict__ bp1, const float* __restrict__ bc1) {
    int i = blockIdx.x * blockDim.x + threadIdx.x;
    if (i < 64 * 128) {
        int k = i >> 7, n = i & 127;
        g_wcomb[i] = (n < 64) ? Wp1[k * 64 + n] : Wc1[k * 64 + n - 64];
    }
    if (i < 128) g_bcomb[i] = (i < 64) ? bp1[i] : bc1[i - 64];
}

// ---------------- graph preprocessing (both graphs batched) ------------------
__global__ void zero_deg_kernel(int n2) {
    int i = blockIdx.x * blockDim.x + threadIdx.x;
    if (i < n2) g_deg[i] = 0;
}

// i in [0, 2E): graph = i/E, edge = i%E. counts into g_deg[g*N + col]
__global__ void hist_kernel(const int* __restrict__ ei1, const int* __restrict__ ei2,
                            int E, int N) {
    int i = blockIdx.x * blockDim.x + threadIdx.x;
    if (i >= 2 * E) return;
    int g = (i >= E);
    int e = i - g * E;
    const int* ei = g ? ei2 : ei1;
    int c = ei[E + e];
    atomicAdd(&g_deg[g * N + c], 1);
}

// Phase A: per-1024-block exclusive scan of g_deg -> g_off, totals -> g_bsum
__global__ void scan_blocks_kernel(int n2) {
    int b = blockIdx.x, tid = threadIdx.x;
    int i = b * 1024 + tid;
    int lane = tid & 31, w = tid >> 5;
    int v = (i < n2) ? g_deg[i] : 0;
    int s = v;
#pragma unroll
    for (int o = 1; o < 32; o <<= 1) {
        int t = __shfl_up_sync(0xffffffffu, s, o);
        if (lane >= o) s += t;
    }
    __shared__ int wsum[32];
    if (lane == 31) wsum[w] = s;
    __syncthreads();
    if (w == 0) {
        int t = wsum[lane];
#pragma unroll
        for (int o = 1; o < 32; o <<= 1) {
            int u = __shfl_up_sync(0xffffffffu, t, o);
            if (lane >= o) t += u;
        }
        wsum[lane] = t;
    }
    __syncthreads();
    int excl = s - v + (w > 0 ? wsum[w - 1] : 0);
    if (i < n2) {
        g_off[i] = excl;
        g_dinv[i] = rsqrtf((float)(v + 1));
    }
    if (tid == 0) g_bsum[b] = wsum[31];
}

// Phase B: scan block totals (nb <= 128)
__global__ void scan_top_kernel(int nb, int n2) {
    int tid = threadIdx.x;   // 128
    __shared__ int sh[128];
    int v = (tid < nb) ? g_bsum[tid] : 0;
    sh[tid] = v;
    __syncthreads();
#pragma unroll
    for (int d = 1; d < 128; d <<= 1) {
        int t = (tid >= d) ? sh[tid - d] : 0;
        __syncthreads();
        sh[tid] += t;
        __syncthreads();
    }
    if (tid < nb) g_bpre[tid] = sh[tid] - v;
    if (tid == 127) g_off[n2] = sh[127];
}

// Phase C: add block prefixes, zero cursors
__global__ void scan_add_kernel(int n2) {
    int i = blockIdx.x * blockDim.x + threadIdx.x;
    if (i < n2) {
        g_off[i] += g_bpre[i >> 10];
        g_cur[i] = 0;
    }
}

// CSR stores GLOBAL source node ids (g*N + r)
__global__ void fill_csr_kernel(const int* __restrict__ ei1, const int* __restrict__ ei2,
                                int E, int N) {
    int i = blockIdx.x * blockDim.x + threadIdx.x;
    if (i >= 2 * E) return;
    int g = (i >= E);
    int e = i - g * E;
    const int* ei = g ? ei2 : ei1;
    int r = ei[e];
    int c = ei[E + e];
    int cg = g * N + c;
    int p = atomicAdd(&g_cur[cg], 1);
    g_csr[g_off[cg] + p] = g * N + r;
}

// ---------------- neighbor aggregation: warp per node, vector rows ------------
// out[node] = relu( dinv[node] * (G[node] + sum_nbr G[nbr]) + bias )
template <int F>
__global__ void agg_warp_kernel(const float* __restrict__ G,
                                const float* __restrict__ bias,
                                float* __restrict__ out, int N2) {
    int node = blockIdx.x * (blockDim.x >> 5) + (threadIdx.x >> 5);
    if (node >= N2) return;
    int lane = threadIdx.x & 31;
    int s = g_off[node], e = g_off[node + 1];

    if constexpr (F == 128) {
        float4 acc = *reinterpret_cast<const float4*>(&G[(size_t)node * F + lane * 4]);
        int j = s;
        for (; j + 4 <= e; j += 4) {
            int n0 = g_csr[j], n1 = g_csr[j + 1], n2 = g_csr[j + 2], n3 = g_csr[j + 3];
            float4 v0 = *reinterpret_cast<const float4*>(&G[(size_t)n0 * F + lane * 4]);
            float4 v1 = *reinterpret_cast<const float4*>(&G[(size_t)n1 * F + lane * 4]);
            float4 v2 = *reinterpret_cast<const float4*>(&G[(size_t)n2 * F + lane * 4]);
            float4 v3 = *reinterpret_cast<const float4*>(&G[(size_t)n3 * F + lane * 4]);
            acc.x += v0.x + v1.x + v2.x + v3.x;
            acc.y += v0.y + v1.y + v2.y + v3.y;
            acc.z += v0.z + v1.z + v2.z + v3.z;
            acc.w += v0.w + v1.w + v2.w + v3.w;
        }
        for (; j < e; j++) {
            float4 v = *reinterpret_cast<const float4*>(&G[(size_t)g_csr[j] * F + lane * 4]);
            acc.x += v.x; acc.y += v.y; acc.z += v.z; acc.w += v.w;
        }
        float d = g_dinv[node];
        float4 bb = *reinterpret_cast<const float4*>(&bias[lane * 4]);
        float4 o;
        o.x = fmaxf(fmaf(d, acc.x, bb.x), 0.f);
        o.y = fmaxf(fmaf(d, acc.y, bb.y), 0.f);
        o.z = fmaxf(fmaf(d, acc.z, bb.z), 0.f);
        o.w = fmaxf(fmaf(d, acc.w, bb.w), 0.f);
        *reinterpret_cast<float4*>(&out[(size_t)node * F + lane * 4]) = o;
    } else {
        float2 acc = *reinterpret_cast<const float2*>(&G[(size_t)node * F + lane * 2]);
        int j = s;
        for (; j + 4 <= e; j += 4) {
            int n0 = g_csr[j], n1 = g_csr[j + 1], n2 = g_csr[j + 2], n3 = g_csr[j + 3];
            float2 v0 = *reinterpret_cast<const float2*>(&G[(size_t)n0 * F + lane * 2]);
            float2 v1 = *reinterpret_cast<const float2*>(&G[(size_t)n1 * F + lane * 2]);
            float2 v2 = *reinterpret_cast<const float2*>(&G[(size_t)n2 * F + lane * 2]);
            float2 v3 = *reinterpret_cast<const float2*>(&G[(size_t)n3 * F + lane * 2]);
            acc.x += v0.x + v1.x + v2.x + v3.x;
            acc.y += v0.y + v1.y + v2.y + v3.y;
        }
        for (; j < e; j++) {
            float2 v = *reinterpret_cast<const float2*>(&G[(size_t)g_csr[j] * F + lane * 2]);
            acc.x += v.x; acc.y += v.y;
        }
        float d = g_dinv[node];
        float2 bb = *reinterpret_cast<const float2*>(&bias[lane * 2]);
        float2 o;
        o.x = fmaxf(fmaf(d, acc.x, bb.x), 0.f);
        o.y = fmaxf(fmaf(d, acc.y, bb.y), 0.f);
        *reinterpret_cast<float2*>(&out[(size_t)node * F + lane * 2]) = o;
    }
}

// ---------------- TF32 tensor-core GEMM --------------------------------------
__device__ __forceinline__ unsigned f2tf32(float x) {
    unsigned r;
    asm("cvt.rna.tf32.f32 %0, %1;" : "=r"(r) : "f"(x));
    return r;
}

__device__ __forceinline__ void mma_tf32(float c[4], const unsigned a[4],
                                         const unsigned b[2]) {
    asm volatile(
        "mma.sync.aligned.m16n8k8.row.col.f32.tf32.tf32.f32 "
        "{%0,%1,%2,%3}, {%4,%5,%6,%7}, {%8,%9}, {%0,%1,%2,%3};"
        : "+f"(c[0]), "+f"(c[1]), "+f"(c[2]), "+f"(c[3])
        : "r"(a[0]), "r"(a[1]), "r"(a[2]), "r"(a[3]), "r"(b[0]), "r"(b[1]));
}

// Core block GEMM: rows [rowBase, rowBase+128) of A (nRows valid in that graph),
// dinv indexed at dinvBase+row. EPI 0/1/2/3 as before.
template <int K, int F, int EPI, int LDA>
__device__ __forceinline__ void gemm_block(
    const float* __restrict__ A, const float* __restrict__ B,
    const float* __restrict__ vec, float* __restrict__ C,
    int rowBase, int nRows, int dinvBase) {
    constexpr int BK = 32;
    constexpr int WN = F / 32;
    constexpr int THREADS = 32 * 2 * WN;
    __shared__ unsigned As[128][36];
    __shared__ unsigned Bs[F][36];

    int tid = threadIdx.x;
    int lane = tid & 31;
    int warp = tid >> 5;
    int warpM = warp / WN;
    int warpN = warp % WN;

    float acc[4][4][4];
#pragma unroll
    for (int i = 0; i < 4; i++)
#pragma unroll
        for (int j = 0; j < 4; j++)
#pragma unroll
            for (int q = 0; q < 4; q++) acc[i][j][q] = 0.0f;

    for (int kc = 0; kc < K; kc += BK) {
        constexpr int AQ = (128 * BK / 4) / THREADS;
#pragma unroll
        for (int q = 0; q < AQ; q++) {
            int lin = tid + q * THREADS;
            int r = lin >> 3;
            int k4 = lin & 7;
            float4 v = make_float4(0.f, 0.f, 0.f, 0.f);
            int gr = rowBase + r;
            if (gr < nRows)
                v = *reinterpret_cast<const float4*>(&A[(size_t)gr * LDA + kc + k4 * 4]);
            uint4 t;
            t.x = f2tf32(v.x); t.y = f2tf32(v.y);
            t.z = f2tf32(v.z); t.w = f2tf32(v.w);
            *reinterpret_cast<uint4*>(&As[r][k4 * 4]) = t;
        }
        {
            int n = tid % F;
            int kg = tid / F;
            constexpr int KPER = BK / (THREADS / F);
#pragma unroll
            for (int q = 0; q < KPER; q++) {
                int kk = kg * KPER + q;
                Bs[n][kk] = f2tf32(B[(size_t)(kc + kk) * F + n]);
            }
        }
        __syncthreads();

#pragma unroll
        for (int ks = 0; ks < BK / 8; ks++) {
            int kA = ks * 8 + (lane & 3);
            unsigned a[4][4], b[4][2];
            int r0 = warpM * 64 + (lane >> 2);
#pragma unroll
            for (int mf = 0; mf < 4; mf++) {
                int rr = r0 + mf * 16;
                a[mf][0] = As[rr][kA];
                a[mf][1] = As[rr + 8][kA];
                a[mf][2] = As[rr][kA + 4];
                a[mf][3] = As[rr + 8][kA + 4];
            }
            int c0 = warpN * 32 + (lane >> 2);
#pragma unroll
            for (int nf = 0; nf < 4; nf++) {
                b[nf][0] = Bs[c0 + nf * 8][kA];
                b[nf][1] = Bs[c0 + nf * 8][kA + 4];
            }
#pragma unroll
            for (int mf = 0; mf < 4; mf++)
#pragma unroll
                for (int nf = 0; nf < 4; nf++) mma_tf32(acc[mf][nf], a[mf], b[nf]);
        }
        __syncthreads();
    }

    int cThr = warpN * 32 + (lane & 3) * 2;

    if constexpr (EPI == 3) {
        __shared__ float ss[128];
        if (tid < 128) ss[tid] = 0.f;
        __syncthreads();
#pragma unroll
        for (int mf = 0; mf < 4; mf++) {
#pragma unroll
            for (int half = 0; half < 2; half++) {
                int lr = warpM * 64 + mf * 16 + half * 8 + (lane >> 2);
                float q = 0.f;
#pragma unroll
                for (int nf = 0; nf < 4; nf++) {
                    int gc = cThr + nf * 8;
                    float v0 = acc[mf][nf][half * 2 + 0] + vec[gc];
                    float v1 = acc[mf][nf][half * 2 + 1] + vec[gc + 1];
                    acc[mf][nf][half * 2 + 0] = v0;
                    acc[mf][nf][half * 2 + 1] = v1;
                    q = fmaf(v0, v0, q);
                    q = fmaf(v1, v1, q);
                }
                atomicAdd(&ss[lr], q);
            }
        }
        __syncthreads();
#pragma unroll
        for (int mf = 0; mf < 4; mf++) {
#pragma unroll
            for (int half = 0; half < 2; half++) {
                int lr = warpM * 64 + mf * 16 + half * 8 + (lane >> 2);
                int gr = rowBase + lr;
                if (gr >= nRows) continue;
                float nrm = sqrtf(ss[lr]);
                float inv = 1.0f / fmaxf(nrm, 1e-12f);
#pragma unroll
                for (int nf = 0; nf < 4; nf++) {
                    int gc = cThr + nf * 8;
                    *reinterpret_cast<float2*>(&C[(size_t)gr * F + gc]) =
                        make_float2(acc[mf][nf][half * 2 + 0] * inv,
                                    acc[mf][nf][half * 2 + 1] * inv);
                }
            }
        }
    } else {
#pragma unroll
        for (int mf = 0; mf < 4; mf++) {
#pragma unroll
            for (int half = 0; half < 2; half++) {
                int gr = rowBase + warpM * 64 + mf * 16 + half * 8 + (lane >> 2);
                if (gr >= nRows) continue;
                float rs = (EPI == 0) ? g_dinv[dinvBase + gr] : 1.0f;
#pragma unroll
                for (int nf = 0; nf < 4; nf++) {
                    int gc = cThr + nf * 8;
                    float v0 = acc[mf][nf][half * 2 + 0];
                    float v1 = acc[mf][nf][half * 2 + 1];
                    if (EPI == 0) { v0 *= rs; v1 *= rs; }
                    else {
                        v0 += vec[gc]; v1 += vec[gc + 1];
                        if (EPI == 1) { v0 = fmaxf(v0, 0.f); v1 = fmaxf(v1, 0.f); }
                    }
                    *reinterpret_cast<float2*>(&C[(size_t)gr * F + gc]) =
                        make_float2(v0, v1);
                }
            }
        }
    }
}

// Single-source GEMM over N2 contiguous rows
template <int K, int F, int EPI, int LDA>
__global__ void gemm_tc(const float* __restrict__ A, const float* __restrict__ B,
                        const float* __restrict__ vec, float* __restrict__ C,
                        int N2) {
    gemm_block<K, F, EPI, LDA>(A, B, vec, C, blockIdx.x * 128, N2, 0);
}

// Dual-source GEMM: grid.y selects graph (A0/A1 separate, C strided by N rows)
template <int K, int F, int EPI, int LDA>
__global__ void gemm_tc_dual(const float* __restrict__ A0, const float* __restrict__ A1,
                             const float* __restrict__ B, const float* __restrict__ vec,
                             float* __restrict__ C, int N) {
    int g = blockIdx.y;
    const float* A = g ? A1 : A0;
    float* Cg = C + (size_t)g * N * F;
    gemm_block<K, F, EPI, LDA>(A, B, vec, Cg, blockIdx.x * 128, N, g * N);
}

// ---------------- fused cluster head: softmax((Hc@Wc2)+bc2) ------------------
__global__ void cluster_kernel(const float* __restrict__ H,
                               const float* __restrict__ Wc2,
                               const float* __restrict__ bc2,
                               float* __restrict__ out, int N2) {
    int gtid = blockIdx.x * blockDim.x + threadIdx.x;
    int node = gtid >> 5;
    int lane = gtid & 31;
    if (node >= N2) return;
    const float* rowp = H + (size_t)node * 128 + 64;
    float d0 = 0.f, d1 = 0.f, d2 = 0.f;
#pragma unroll
    for (int kb = 0; kb < 2; kb++) {
        int k = lane + kb * 32;
        float v = rowp[k];
        d0 = fmaf(v, Wc2[k * 3 + 0], d0);
        d1 = fmaf(v, Wc2[k * 3 + 1], d1);
        d2 = fmaf(v, Wc2[k * 3 + 2], d2);
    }
#pragma unroll
    for (int o = 16; o > 0; o >>= 1) {
        d0 += __shfl_down_sync(0xffffffffu, d0, o);
        d1 += __shfl_down_sync(0xffffffffu, d1, o);
        d2 += __shfl_down_sync(0xffffffffu, d2, o);
    }
    if (lane == 0) {
        d0 += bc2[0]; d1 += bc2[1]; d2 += bc2[2];
        float m = fmaxf(d0, fmaxf(d1, d2));
        float e0 = __expf(d0 - m), e1 = __expf(d1 - m), e2 = __expf(d2 - m);
        float inv = 1.0f / (e0 + e1 + e2);
        out[(size_t)node * 3 + 0] = e0 * inv;
        out[(size_t)node * 3 + 1] = e1 * inv;
        out[(size_t)node * 3 + 2] = e2 * inv;
    }
}

// ---------------- launch -----------------------------------------------------
extern "C" void kernel_launch(void* const* d_in, const int* in_sizes, int n_in,
                              void* d_out, int out_size) {
    const float* x1  = (const float*)d_in[0];
    const int*   ei1 = (const int*)  d_in[1];
    const float* x2  = (const float*)d_in[2];
    const int*   ei2 = (const int*)  d_in[3];
    const float* W1  = (const float*)d_in[4];
    const float* b1  = (const float*)d_in[5];
    const float* W2  = (const float*)d_in[6];
    const float* b2  = (const float*)d_in[7];
    const float* Wp1 = (const float*)d_in[8];
    const float* bp1 = (const float*)d_in[9];
    const float* Wp2 = (const float*)d_in[10];
    const float* bp2 = (const float*)d_in[11];
    const float* Wc1 = (const float*)d_in[12];
    const float* bc1 = (const float*)d_in[13];
    const float* Wc2 = (const float*)d_in[14];
    const float* bc2 = (const float*)d_in[15];

    int N = in_sizes[0] / 128;
    int E = in_sizes[1] / 2;
    int N2 = 2 * N;
    int E2 = 2 * E;

    float* out = (float*)d_out;
    float* out_z = out;                       // z_i then z_j, contiguous
    float* out_c = out + (size_t)N2 * 128;    // c_i then c_j, contiguous

    void *pA, *pB, *pC, *pW, *pBi;
    cudaGetSymbolAddress(&pA, g_bufA);
    cudaGetSymbolAddress(&pB, g_bufB);
    cudaGetSymbolAddress(&pC, g_bufC);
    cudaGetSymbolAddress(&pW, g_wcomb);
    cudaGetSymbolAddress(&pBi, g_bcomb);
    float* bufA = (float*)pA;
    float* bufB = (float*)pB;
    float* bufC = (float*)pC;
    float* wcomb = (float*)pW;
    float* bcomb = (float*)pBi;

    int gemmGridN  = (N + 127) / 128;    // per-graph blocks (dual kernel)
    int gemmGridN2 = (N2 + 127) / 128;   // batched blocks
    int scanBlocks = (N2 + 1023) / 1024;

    combine_wb<<<(64 * 128 + 255) / 256, 256>>>(Wp1, Wc1, bp1, bc1);

    // ---- preprocessing, both graphs batched ----
    zero_deg_kernel<<<(N2 + 255) / 256, 256>>>(N2);
    hist_kernel<<<(E2 + 255) / 256, 256>>>(ei1, ei2, E, N);
    scan_blocks_kernel<<<scanBlocks, 1024>>>(N2);
    scan_top_kernel<<<1, 128>>>(scanBlocks, N2);
    scan_add_kernel<<<(N2 + 255) / 256, 256>>>(N2);
    fill_csr_kernel<<<(E2 + 255) / 256, 256>>>(ei1, ei2, E, N);

    // ---- GCN layer 1 (dual-source GEMM, then batched agg) ----
    dim3 grid1(gemmGridN, 2);
    gemm_tc_dual<128, 128, 0, 128><<<grid1, 256>>>(x1, x2, W1, nullptr, bufA, N);
    agg_warp_kernel<128><<<(N2 + 7) / 8, 256>>>(bufA, b1, bufB, N2);

    // ---- GCN layer 2 (batched over 2N) ----
    gemm_tc<128, 64, 0, 128><<<gemmGridN2, 128>>>(bufB, W2, nullptr, bufA, N2);
    agg_warp_kernel<64><<<(N2 + 7) / 8, 256>>>(bufA, b2, bufC, N2);

    // ---- combined projector: [P | Hc] = relu(Z @ [Wp1|Wc1] + [bp1|bc1]) ----
    gemm_tc<64, 128, 1, 64><<<gemmGridN2, 256>>>(bufC, wcomb, bcomb, bufB, N2);

    // ---- instance head: l2norm(P @ Wp2 + bp2) fused ----
    gemm_tc<64, 128, 3, 128><<<gemmGridN2, 256>>>(bufB, Wp2, bp2, out_z, N2);

    // ---- cluster head: softmax(Hc @ Wc2 + bc2) ----
    cluster_kernel<<<((N2 * 32) + 255) / 256, 256>>>(bufB, Wc2, bc2, out_c, N2);
}

// round 6
// speedup vs baseline: 2.8789x; 1.1242x over previous
#include <cuda_runtime.h>
#include <cuda_fp16.h>
#include <math.h>

#define NMAX 50000
#define EMAX 800000
#define N2MAX (2 * NMAX)
#define E2MAX (2 * EMAX)

// ---------------- scratch (static device globals; no allocation) ------------
__device__ __half g_bufA[N2MAX * 128];   // GEMM outputs (pre-agg), fp16
__device__ __half g_bufB[N2MAX * 128];   // agg1 output / projector hidden, fp16
__device__ __half g_bufC[N2MAX * 64];    // encoder output Z, fp16
__device__ float  g_dinv[N2MAX];
__device__ int    g_deg[N2MAX];
__device__ int    g_off[N2MAX + 1];
__device__ int    g_cur[N2MAX];
__device__ int    g_csr[E2MAX];
__device__ int    g_bsum[128];
__device__ int    g_bpre[128];
__device__ float  g_wcomb[64 * 128];   // [Wp1 | Wc1]
__device__ float  g_bcomb[128];        // [bp1 | bc1]

// ---------------- fp16 helpers ----------------------------------------------
__device__ __forceinline__ float4 ld_half4(const __half* p) {
    uint2 r = *reinterpret_cast<const uint2*>(p);
    __half2 h0 = *reinterpret_cast<__half2*>(&r.x);
    __half2 h1 = *reinterpret_cast<__half2*>(&r.y);
    float2 f0 = __half22float2(h0), f1 = __half22float2(h1);
    return make_float4(f0.x, f0.y, f1.x, f1.y);
}
__device__ __forceinline__ void st_half4(__half* p, float4 v) {
    __half2 h0 = __floats2half2_rn(v.x, v.y);
    __half2 h1 = __floats2half2_rn(v.z, v.w);
    uint2 r;
    r.x = *reinterpret_cast<unsigned*>(&h0);
    r.y = *reinterpret_cast<unsigned*>(&h1);
    *reinterpret_cast<uint2*>(p) = r;
}

// ---------------- weight concat (once per call) ------------------------------
__global__ void combine_wb(const float* __restrict__ Wp1, const float* __restrict__ Wc1,
                           const float* __restrict__ bp1, const float* __restrict__ bc1) {
    int i = blockIdx.x * blockDim.x + threadIdx.x;
    if (i < 64 * 128) {
        int k = i >> 7, n = i & 127;
        g_wcomb[i] = (n < 64) ? Wp1[k * 64 + n] : Wc1[k * 64 + n - 64];
    }
    if (i < 128) g_bcomb[i] = (i < 64) ? bp1[i] : bc1[i - 64];
}

// ---------------- graph preprocessing (both graphs batched) ------------------
__global__ void zero_deg_kernel(int n2) {
    int i = blockIdx.x * blockDim.x + threadIdx.x;
    if (i < n2) g_deg[i] = 0;
}

__global__ void hist_kernel(const int* __restrict__ ei1, const int* __restrict__ ei2,
                            int E, int N) {
    int i = blockIdx.x * blockDim.x + threadIdx.x;
    if (i >= 2 * E) return;
    int g = (i >= E);
    int e = i - g * E;
    const int* ei = g ? ei2 : ei1;
    int c = ei[E + e];
    atomicAdd(&g_deg[g * N + c], 1);
}

__global__ void scan_blocks_kernel(int n2) {
    int b = blockIdx.x, tid = threadIdx.x;
    int i = b * 1024 + tid;
    int lane = tid & 31, w = tid >> 5;
    int v = (i < n2) ? g_deg[i] : 0;
    int s = v;
#pragma unroll
    for (int o = 1; o < 32; o <<= 1) {
        int t = __shfl_up_sync(0xffffffffu, s, o);
        if (lane >= o) s += t;
    }
    __shared__ int wsum[32];
    if (lane == 31) wsum[w] = s;
    __syncthreads();
    if (w == 0) {
        int t = wsum[lane];
#pragma unroll
        for (int o = 1; o < 32; o <<= 1) {
            int u = __shfl_up_sync(0xffffffffu, t, o);
            if (lane >= o) t += u;
        }
        wsum[lane] = t;
    }
    __syncthreads();
    int excl = s - v + (w > 0 ? wsum[w - 1] : 0);
    if (i < n2) {
        g_off[i] = excl;
        g_dinv[i] = rsqrtf((float)(v + 1));
    }
    if (tid == 0) g_bsum[b] = wsum[31];
}

__global__ void scan_top_kernel(int nb, int n2) {
    int tid = threadIdx.x;   // 128
    __shared__ int sh[128];
    int v = (tid < nb) ? g_bsum[tid] : 0;
    sh[tid] = v;
    __syncthreads();
#pragma unroll
    for (int d = 1; d < 128; d <<= 1) {
        int t = (tid >= d) ? sh[tid - d] : 0;
        __syncthreads();
        sh[tid] += t;
        __syncthreads();
    }
    if (tid < nb) g_bpre[tid] = sh[tid] - v;
    if (tid == 127) g_off[n2] = sh[127];
}

__global__ void scan_add_kernel(int n2) {
    int i = blockIdx.x * blockDim.x + threadIdx.x;
    if (i < n2) {
        g_off[i] += g_bpre[i >> 10];
        g_cur[i] = 0;
    }
}

__global__ void fill_csr_kernel(const int* __restrict__ ei1, const int* __restrict__ ei2,
                                int E, int N) {
    int i = blockIdx.x * blockDim.x + threadIdx.x;
    if (i >= 2 * E) return;
    int g = (i >= E);
    int e = i - g * E;
    const int* ei = g ? ei2 : ei1;
    int r = ei[e];
    int c = ei[E + e];
    int cg = g * N + c;
    int p = atomicAdd(&g_cur[cg], 1);
    g_csr[g_off[cg] + p] = g * N + r;
}

// ---------------- neighbor aggregation: warp per node, fp16 rows --------------
// out[node] = relu( dinv[node] * (G[node] + sum_nbr G[nbr]) + bias )
template <int F>
__global__ void agg_warp_kernel(const __half* __restrict__ G,
                                const float* __restrict__ bias,
                                __half* __restrict__ out, int N2) {
    int node = blockIdx.x * (blockDim.x >> 5) + (threadIdx.x >> 5);
    if (node >= N2) return;
    int lane = threadIdx.x & 31;
    int s = g_off[node], e = g_off[node + 1];

    if constexpr (F == 128) {
        float4 acc = ld_half4(&G[(size_t)node * F + lane * 4]);
        int j = s;
        for (; j + 4 <= e; j += 4) {
            int n0 = g_csr[j], n1 = g_csr[j + 1], n2 = g_csr[j + 2], n3 = g_csr[j + 3];
            float4 v0 = ld_half4(&G[(size_t)n0 * F + lane * 4]);
            float4 v1 = ld_half4(&G[(size_t)n1 * F + lane * 4]);
            float4 v2 = ld_half4(&G[(size_t)n2 * F + lane * 4]);
            float4 v3 = ld_half4(&G[(size_t)n3 * F + lane * 4]);
            acc.x += v0.x + v1.x + v2.x + v3.x;
            acc.y += v0.y + v1.y + v2.y + v3.y;
            acc.z += v0.z + v1.z + v2.z + v3.z;
            acc.w += v0.w + v1.w + v2.w + v3.w;
        }
        for (; j < e; j++) {
            float4 v = ld_half4(&G[(size_t)g_csr[j] * F + lane * 4]);
            acc.x += v.x; acc.y += v.y; acc.z += v.z; acc.w += v.w;
        }
        float d = g_dinv[node];
        float4 bb = *reinterpret_cast<const float4*>(&bias[lane * 4]);
        float4 o;
        o.x = fmaxf(fmaf(d, acc.x, bb.x), 0.f);
        o.y = fmaxf(fmaf(d, acc.y, bb.y), 0.f);
        o.z = fmaxf(fmaf(d, acc.z, bb.z), 0.f);
        o.w = fmaxf(fmaf(d, acc.w, bb.w), 0.f);
        st_half4(&out[(size_t)node * F + lane * 4], o);
    } else {
        __half2 h = *reinterpret_cast<const __half2*>(&G[(size_t)node * F + lane * 2]);
        float2 acc = __half22float2(h);
        int j = s;
        for (; j + 4 <= e; j += 4) {
            int n0 = g_csr[j], n1 = g_csr[j + 1], n2 = g_csr[j + 2], n3 = g_csr[j + 3];
            float2 v0 = __half22float2(*reinterpret_cast<const __half2*>(&G[(size_t)n0 * F + lane * 2]));
            float2 v1 = __half22float2(*reinterpret_cast<const __half2*>(&G[(size_t)n1 * F + lane * 2]));
            float2 v2 = __half22float2(*reinterpret_cast<const __half2*>(&G[(size_t)n2 * F + lane * 2]));
            float2 v3 = __half22float2(*reinterpret_cast<const __half2*>(&G[(size_t)n3 * F + lane * 2]));
            acc.x += v0.x + v1.x + v2.x + v3.x;
            acc.y += v0.y + v1.y + v2.y + v3.y;
        }
        for (; j < e; j++) {
            float2 v = __half22float2(*reinterpret_cast<const __half2*>(&G[(size_t)g_csr[j] * F + lane * 2]));
            acc.x += v.x; acc.y += v.y;
        }
        float d = g_dinv[node];
        float2 bb = *reinterpret_cast<const float2*>(&bias[lane * 2]);
        float ox = fmaxf(fmaf(d, acc.x, bb.x), 0.f);
        float oy = fmaxf(fmaf(d, acc.y, bb.y), 0.f);
        *reinterpret_cast<__half2*>(&out[(size_t)node * F + lane * 2]) =
            __floats2half2_rn(ox, oy);
    }
}

// ---------------- TF32 tensor-core GEMM --------------------------------------
__device__ __forceinline__ unsigned f2tf32(float x) {
    unsigned r;
    asm("cvt.rna.tf32.f32 %0, %1;" : "=r"(r) : "f"(x));
    return r;
}

__device__ __forceinline__ void mma_tf32(float c[4], const unsigned a[4],
                                         const unsigned b[2]) {
    asm volatile(
        "mma.sync.aligned.m16n8k8.row.col.f32.tf32.tf32.f32 "
        "{%0,%1,%2,%3}, {%4,%5,%6,%7}, {%8,%9}, {%0,%1,%2,%3};"
        : "+f"(c[0]), "+f"(c[1]), "+f"(c[2]), "+f"(c[3])
        : "r"(a[0]), "r"(a[1]), "r"(a[2]), "r"(a[3]), "r"(b[0]), "r"(b[1]));
}

// Core block GEMM. AT: float or __half (A source). CT: float or __half (C dest).
// EPI 0: out = acc * g_dinv[dinvBase+row]
// EPI 1: out = relu(acc + vec[col])
// EPI 3: out = l2norm_row(acc + vec[col])   (F==128, CT=float)
template <int K, int F, int EPI, int LDA, typename AT, typename CT>
__device__ __forceinline__ void gemm_block(
    const AT* __restrict__ A, const float* __restrict__ B,
    const float* __restrict__ vec, CT* __restrict__ C,
    int rowBase, int nRows, int dinvBase) {
    constexpr int BK = 32;
    constexpr int WN = F / 32;
    constexpr int THREADS = 32 * 2 * WN;
    __shared__ unsigned As[128][36];
    __shared__ unsigned Bs[F][36];

    int tid = threadIdx.x;
    int lane = tid & 31;
    int warp = tid >> 5;
    int warpM = warp / WN;
    int warpN = warp % WN;

    float acc[4][4][4];
#pragma unroll
    for (int i = 0; i < 4; i++)
#pragma unroll
        for (int j = 0; j < 4; j++)
#pragma unroll
            for (int q = 0; q < 4; q++) acc[i][j][q] = 0.0f;

    for (int kc = 0; kc < K; kc += BK) {
        constexpr int AQ = (128 * BK / 4) / THREADS;
#pragma unroll
        for (int q = 0; q < AQ; q++) {
            int lin = tid + q * THREADS;
            int r = lin >> 3;
            int k4 = lin & 7;
            float4 v = make_float4(0.f, 0.f, 0.f, 0.f);
            int gr = rowBase + r;
            if (gr < nRows) {
                if constexpr (sizeof(AT) == 4)
                    v = *reinterpret_cast<const float4*>(&A[(size_t)gr * LDA + kc + k4 * 4]);
                else
                    v = ld_half4(&A[(size_t)gr * LDA + kc + k4 * 4]);
            }
            uint4 t;
            t.x = f2tf32(v.x); t.y = f2tf32(v.y);
            t.z = f2tf32(v.z); t.w = f2tf32(v.w);
            *reinterpret_cast<uint4*>(&As[r][k4 * 4]) = t;
        }
        {
            int n = tid % F;
            int kg = tid / F;
            constexpr int KPER = BK / (THREADS / F);
#pragma unroll
            for (int q = 0; q < KPER; q++) {
                int kk = kg * KPER + q;
                Bs[n][kk] = f2tf32(B[(size_t)(kc + kk) * F + n]);
            }
        }
        __syncthreads();

#pragma unroll
        for (int ks = 0; ks < BK / 8; ks++) {
            int kA = ks * 8 + (lane & 3);
            unsigned a[4][4], b[4][2];
            int r0 = warpM * 64 + (lane >> 2);
#pragma unroll
            for (int mf = 0; mf < 4; mf++) {
                int rr = r0 + mf * 16;
                a[mf][0] = As[rr][kA];
                a[mf][1] = As[rr + 8][kA];
                a[mf][2] = As[rr][kA + 4];
                a[mf][3] = As[rr + 8][kA + 4];
            }
            int c0 = warpN * 32 + (lane >> 2);
#pragma unroll
            for (int nf = 0; nf < 4; nf++) {
                b[nf][0] = Bs[c0 + nf * 8][kA];
                b[nf][1] = Bs[c0 + nf * 8][kA + 4];
            }
#pragma unroll
            for (int mf = 0; mf < 4; mf++)
#pragma unroll
                for (int nf = 0; nf < 4; nf++) mma_tf32(acc[mf][nf], a[mf], b[nf]);
        }
        __syncthreads();
    }

    int cThr = warpN * 32 + (lane & 3) * 2;

    if constexpr (EPI == 3) {
        __shared__ float ss[128];
        if (tid < 128) ss[tid] = 0.f;
        __syncthreads();
#pragma unroll
        for (int mf = 0; mf < 4; mf++) {
#pragma unroll
            for (int half = 0; half < 2; half++) {
                int lr = warpM * 64 + mf * 16 + half * 8 + (lane >> 2);
                float q = 0.f;
#pragma unroll
                for (int nf = 0; nf < 4; nf++) {
                    int gc = cThr + nf * 8;
                    float v0 = acc[mf][nf][half * 2 + 0] + vec[gc];
                    float v1 = acc[mf][nf][half * 2 + 1] + vec[gc + 1];
                    acc[mf][nf][half * 2 + 0] = v0;
                    acc[mf][nf][half * 2 + 1] = v1;
                    q = fmaf(v0, v0, q);
                    q = fmaf(v1, v1, q);
                }
                atomicAdd(&ss[lr], q);
            }
        }
        __syncthreads();
#pragma unroll
        for (int mf = 0; mf < 4; mf++) {
#pragma unroll
            for (int half = 0; half < 2; half++) {
                int lr = warpM * 64 + mf * 16 + half * 8 + (lane >> 2);
                int gr = rowBase + lr;
                if (gr >= nRows) continue;
                float nrm = sqrtf(ss[lr]);
                float inv = 1.0f / fmaxf(nrm, 1e-12f);
#pragma unroll
                for (int nf = 0; nf < 4; nf++) {
                    int gc = cThr + nf * 8;
                    *reinterpret_cast<float2*>(&((float*)C)[(size_t)gr * F + gc]) =
                        make_float2(acc[mf][nf][half * 2 + 0] * inv,
                                    acc[mf][nf][half * 2 + 1] * inv);
                }
            }
        }
    } else {
#pragma unroll
        for (int mf = 0; mf < 4; mf++) {
#pragma unroll
            for (int half = 0; half < 2; half++) {
                int gr = rowBase + warpM * 64 + mf * 16 + half * 8 + (lane >> 2);
                if (gr >= nRows) continue;
                float rs = (EPI == 0) ? g_dinv[dinvBase + gr] : 1.0f;
#pragma unroll
                for (int nf = 0; nf < 4; nf++) {
                    int gc = cThr + nf * 8;
                    float v0 = acc[mf][nf][half * 2 + 0];
                    float v1 = acc[mf][nf][half * 2 + 1];
                    if (EPI == 0) { v0 *= rs; v1 *= rs; }
                    else {
                        v0 += vec[gc]; v1 += vec[gc + 1];
                        if (EPI == 1) { v0 = fmaxf(v0, 0.f); v1 = fmaxf(v1, 0.f); }
                    }
                    if constexpr (sizeof(CT) == 4)
                        *reinterpret_cast<float2*>(&((float*)C)[(size_t)gr * F + gc]) =
                            make_float2(v0, v1);
                    else
                        *reinterpret_cast<__half2*>(&((__half*)C)[(size_t)gr * F + gc]) =
                            __floats2half2_rn(v0, v1);
                }
            }
        }
    }
}

template <int K, int F, int EPI, int LDA, typename AT, typename CT>
__global__ void gemm_tc(const AT* __restrict__ A, const float* __restrict__ B,
                        const float* __restrict__ vec, CT* __restrict__ C,
                        int N2) {
    gemm_block<K, F, EPI, LDA, AT, CT>(A, B, vec, C, blockIdx.x * 128, N2, 0);
}

template <int K, int F, int EPI, int LDA>
__global__ void gemm_tc_dual(const float* __restrict__ A0, const float* __restrict__ A1,
                             const float* __restrict__ B, const float* __restrict__ vec,
                             __half* __restrict__ C, int N) {
    int g = blockIdx.y;
    const float* A = g ? A1 : A0;
    __half* Cg = C + (size_t)g * N * F;
    gemm_block<K, F, EPI, LDA, float, __half>(A, B, vec, Cg, blockIdx.x * 128, N, g * N);
}

// ---------------- fused cluster head: softmax((Hc@Wc2)+bc2) ------------------
// Hc rows are fp16 at H + node*128 + 64 (64 halfs)
__global__ void cluster_kernel(const __half* __restrict__ H,
                               const float* __restrict__ Wc2,
                               const float* __restrict__ bc2,
                               float* __restrict__ out, int N2) {
    int gtid = blockIdx.x * blockDim.x + threadIdx.x;
    int node = gtid >> 5;
    int lane = gtid & 31;
    if (node >= N2) return;
    const __half* rowp = H + (size_t)node * 128 + 64;
    float2 v = __half22float2(*reinterpret_cast<const __half2*>(&rowp[lane * 2]));
    int k0 = lane * 2;
    float d0 = v.x * Wc2[k0 * 3 + 0] + v.y * Wc2[(k0 + 1) * 3 + 0];
    float d1 = v.x * Wc2[k0 * 3 + 1] + v.y * Wc2[(k0 + 1) * 3 + 1];
    float d2 = v.x * Wc2[k0 * 3 + 2] + v.y * Wc2[(k0 + 1) * 3 + 2];
#pragma unroll
    for (int o = 16; o > 0; o >>= 1) {
        d0 += __shfl_down_sync(0xffffffffu, d0, o);
        d1 += __shfl_down_sync(0xffffffffu, d1, o);
        d2 += __shfl_down_sync(0xffffffffu, d2, o);
    }
    if (lane == 0) {
        d0 += bc2[0]; d1 += bc2[1]; d2 += bc2[2];
        float m = fmaxf(d0, fmaxf(d1, d2));
        float e0 = __expf(d0 - m), e1 = __expf(d1 - m), e2 = __expf(d2 - m);
        float inv = 1.0f / (e0 + e1 + e2);
        out[(size_t)node * 3 + 0] = e0 * inv;
        out[(size_t)node * 3 + 1] = e1 * inv;
        out[(size_t)node * 3 + 2] = e2 * inv;
    }
}

// ---------------- launch -----------------------------------------------------
extern "C" void kernel_launch(void* const* d_in, const int* in_sizes, int n_in,
                              void* d_out, int out_size) {
    const float* x1  = (const float*)d_in[0];
    const int*   ei1 = (const int*)  d_in[1];
    const float* x2  = (const float*)d_in[2];
    const int*   ei2 = (const int*)  d_in[3];
    const float* W1  = (const float*)d_in[4];
    const float* b1  = (const float*)d_in[5];
    const float* W2  = (const float*)d_in[6];
    const float* b2  = (const float*)d_in[7];
    const float* Wp1 = (const float*)d_in[8];
    const float* bp1 = (const float*)d_in[9];
    const float* Wp2 = (const float*)d_in[10];
    const float* bp2 = (const float*)d_in[11];
    const float* Wc1 = (const float*)d_in[12];
    const float* bc1 = (const float*)d_in[13];
    const float* Wc2 = (const float*)d_in[14];
    const float* bc2 = (const float*)d_in[15];

    int N = in_sizes[0] / 128;
    int E = in_sizes[1] / 2;
    int N2 = 2 * N;
    int E2 = 2 * E;

    float* out = (float*)d_out;
    float* out_z = out;                       // z_i then z_j, contiguous
    float* out_c = out + (size_t)N2 * 128;    // c_i then c_j, contiguous

    void *pA, *pB, *pC, *pW, *pBi;
    cudaGetSymbolAddress(&pA, g_bufA);
    cudaGetSymbolAddress(&pB, g_bufB);
    cudaGetSymbolAddress(&pC, g_bufC);
    cudaGetSymbolAddress(&pW, g_wcomb);
    cudaGetSymbolAddress(&pBi, g_bcomb);
    __half* bufA = (__half*)pA;
    __half* bufB = (__half*)pB;
    __half* bufC = (__half*)pC;
    float* wcomb = (float*)pW;
    float* bcomb = (float*)pBi;

    int gemmGridN  = (N + 127) / 128;
    int gemmGridN2 = (N2 + 127) / 128;
    int scanBlocks = (N2 + 1023) / 1024;

    combine_wb<<<(64 * 128 + 255) / 256, 256>>>(Wp1, Wc1, bp1, bc1);

    // ---- preprocessing, both graphs batched ----
    zero_deg_kernel<<<(N2 + 255) / 256, 256>>>(N2);
    hist_kernel<<<(E2 + 255) / 256, 256>>>(ei1, ei2, E, N);
    scan_blocks_kernel<<<scanBlocks, 1024>>>(N2);
    scan_top_kernel<<<1, 128>>>(scanBlocks, N2);
    scan_add_kernel<<<(N2 + 255) / 256, 256>>>(N2);
    fill_csr_kernel<<<(E2 + 255) / 256, 256>>>(ei1, ei2, E, N);

    // ---- GCN layer 1 ----
    dim3 grid1(gemmGridN, 2);
    gemm_tc_dual<128, 128, 0, 128><<<grid1, 256>>>(x1, x2, W1, nullptr, bufA, N);
    agg_warp_kernel<128><<<(N2 + 7) / 8, 256>>>(bufA, b1, bufB, N2);

    // ---- GCN layer 2 ----
    gemm_tc<128, 64, 0, 128, __half, __half><<<gemmGridN2, 128>>>(bufB, W2, nullptr, bufA, N2);
    agg_warp_kernel<64><<<(N2 + 7) / 8, 256>>>(bufA, b2, bufC, N2);

    // ---- combined projector: [P | Hc] = relu(Z @ [Wp1|Wc1] + [bp1|bc1]) ----
    gemm_tc<64, 128, 1, 64, __half, __half><<<gemmGridN2, 256>>>(bufC, wcomb, bcomb, bufB, N2);

    // ---- instance head: l2norm(P @ Wp2 + bp2) fused ----
    gemm_tc<64, 128, 3, 128, __half, float><<<gemmGridN2, 256>>>(bufB, Wp2, bp2, out_z, N2);

    // ---- cluster head: softmax(Hc @ Wc2 + bc2) ----
    cluster_kernel<<<((N2 * 32) + 255) / 256, 256>>>(bufB, Wc2, bc2, out_c, N2);
}

// round 7
// speedup vs baseline: 3.1280x; 1.0865x over previous
#include <cuda_runtime.h>
#include <cuda_fp16.h>
#include <math.h>

#define NMAX 50000
#define EMAX 800000
#define N2MAX (2 * NMAX)
#define E2MAX (2 * EMAX)

// ---------------- scratch (static device globals; no allocation) ------------
__device__ __half g_bufA[N2MAX * 128];   // GEMM outputs (pre-agg), fp16
__device__ __half g_bufB[N2MAX * 128];   // agg1 output / projector hidden, fp16
__device__ __half g_bufC[N2MAX * 64];    // encoder output Z, fp16
__device__ float  g_dinv[N2MAX];
__device__ int    g_deg[N2MAX];
__device__ int    g_off[N2MAX + 1];
__device__ int    g_cur[N2MAX];
__device__ int    g_csr[E2MAX];
__device__ int    g_bsum[128];
__device__ int    g_bpre[128];
__device__ float  g_wcomb[64 * 128];   // [Wp1 | Wc1]
__device__ float  g_bcomb[128];        // [bp1 | bc1]

// ---------------- fp16 helpers ----------------------------------------------
__device__ __forceinline__ float4 ld_half4(const __half* p) {
    uint2 r = *reinterpret_cast<const uint2*>(p);
    __half2 h0 = *reinterpret_cast<__half2*>(&r.x);
    __half2 h1 = *reinterpret_cast<__half2*>(&r.y);
    float2 f0 = __half22float2(h0), f1 = __half22float2(h1);
    return make_float4(f0.x, f0.y, f1.x, f1.y);
}
__device__ __forceinline__ void st_half4(__half* p, float4 v) {
    __half2 h0 = __floats2half2_rn(v.x, v.y);
    __half2 h1 = __floats2half2_rn(v.z, v.w);
    uint2 r;
    r.x = *reinterpret_cast<unsigned*>(&h0);
    r.y = *reinterpret_cast<unsigned*>(&h1);
    *reinterpret_cast<uint2*>(p) = r;
}
__device__ __forceinline__ unsigned pack_half2(float a, float b) {
    __half2 h = __floats2half2_rn(a, b);
    return *reinterpret_cast<unsigned*>(&h);
}

// ---------------- weight concat (once per call) ------------------------------
__global__ void combine_wb(const float* __restrict__ Wp1, const float* __restrict__ Wc1,
                           const float* __restrict__ bp1, const float* __restrict__ bc1) {
    int i = blockIdx.x * blockDim.x + threadIdx.x;
    if (i < 64 * 128) {
        int k = i >> 7, n = i & 127;
        g_wcomb[i] = (n < 64) ? Wp1[k * 64 + n] : Wc1[k * 64 + n - 64];
    }
    if (i < 128) g_bcomb[i] = (i < 64) ? bp1[i] : bc1[i - 64];
}

// ---------------- graph preprocessing (both graphs batched) ------------------
__global__ void zero_deg_kernel(int n2) {
    int i = blockIdx.x * blockDim.x + threadIdx.x;
    if (i < n2) g_deg[i] = 0;
}

__global__ void hist_kernel(const int* __restrict__ ei1, const int* __restrict__ ei2,
                            int E, int N) {
    int i = blockIdx.x * blockDim.x + threadIdx.x;
    if (i >= 2 * E) return;
    int g = (i >= E);
    int e = i - g * E;
    const int* ei = g ? ei2 : ei1;
    int c = ei[E + e];
    atomicAdd(&g_deg[g * N + c], 1);
}

__global__ void scan_blocks_kernel(int n2) {
    int b = blockIdx.x, tid = threadIdx.x;
    int i = b * 1024 + tid;
    int lane = tid & 31, w = tid >> 5;
    int v = (i < n2) ? g_deg[i] : 0;
    int s = v;
#pragma unroll
    for (int o = 1; o < 32; o <<= 1) {
        int t = __shfl_up_sync(0xffffffffu, s, o);
        if (lane >= o) s += t;
    }
    __shared__ int wsum[32];
    if (lane == 31) wsum[w] = s;
    __syncthreads();
    if (w == 0) {
        int t = wsum[lane];
#pragma unroll
        for (int o = 1; o < 32; o <<= 1) {
            int u = __shfl_up_sync(0xffffffffu, t, o);
            if (lane >= o) t += u;
        }
        wsum[lane] = t;
    }
    __syncthreads();
    int excl = s - v + (w > 0 ? wsum[w - 1] : 0);
    if (i < n2) {
        g_off[i] = excl;
        g_dinv[i] = rsqrtf((float)(v + 1));
    }
    if (tid == 0) g_bsum[b] = wsum[31];
}

__global__ void scan_top_kernel(int nb, int n2) {
    int tid = threadIdx.x;   // 128
    __shared__ int sh[128];
    int v = (tid < nb) ? g_bsum[tid] : 0;
    sh[tid] = v;
    __syncthreads();
#pragma unroll
    for (int d = 1; d < 128; d <<= 1) {
        int t = (tid >= d) ? sh[tid - d] : 0;
        __syncthreads();
        sh[tid] += t;
        __syncthreads();
    }
    if (tid < nb) g_bpre[tid] = sh[tid] - v;
    if (tid == 127) g_off[n2] = sh[127];
}

__global__ void scan_add_kernel(int n2) {
    int i = blockIdx.x * blockDim.x + threadIdx.x;
    if (i < n2) {
        g_off[i] += g_bpre[i >> 10];
        g_cur[i] = 0;
    }
}

__global__ void fill_csr_kernel(const int* __restrict__ ei1, const int* __restrict__ ei2,
                                int E, int N) {
    int i = blockIdx.x * blockDim.x + threadIdx.x;
    if (i >= 2 * E) return;
    int g = (i >= E);
    int e = i - g * E;
    const int* ei = g ? ei2 : ei1;
    int r = ei[e];
    int c = ei[E + e];
    int cg = g * N + c;
    int p = atomicAdd(&g_cur[cg], 1);
    g_csr[g_off[cg] + p] = g * N + r;
}

// ---------------- neighbor aggregation: warp per node, fp16 rows --------------
template <int F>
__global__ void agg_warp_kernel(const __half* __restrict__ G,
                                const float* __restrict__ bias,
                                __half* __restrict__ out, int N2) {
    int node = blockIdx.x * (blockDim.x >> 5) + (threadIdx.x >> 5);
    if (node >= N2) return;
    int lane = threadIdx.x & 31;
    int s = g_off[node], e = g_off[node + 1];

    if constexpr (F == 128) {
        float4 acc = ld_half4(&G[(size_t)node * F + lane * 4]);
        int j = s;
        for (; j + 4 <= e; j += 4) {
            int n0 = g_csr[j], n1 = g_csr[j + 1], n2 = g_csr[j + 2], n3 = g_csr[j + 3];
            float4 v0 = ld_half4(&G[(size_t)n0 * F + lane * 4]);
            float4 v1 = ld_half4(&G[(size_t)n1 * F + lane * 4]);
            float4 v2 = ld_half4(&G[(size_t)n2 * F + lane * 4]);
            float4 v3 = ld_half4(&G[(size_t)n3 * F + lane * 4]);
            acc.x += v0.x + v1.x + v2.x + v3.x;
            acc.y += v0.y + v1.y + v2.y + v3.y;
            acc.z += v0.z + v1.z + v2.z + v3.z;
            acc.w += v0.w + v1.w + v2.w + v3.w;
        }
        for (; j < e; j++) {
            float4 v = ld_half4(&G[(size_t)g_csr[j] * F + lane * 4]);
            acc.x += v.x; acc.y += v.y; acc.z += v.z; acc.w += v.w;
        }
        float d = g_dinv[node];
        float4 bb = *reinterpret_cast<const float4*>(&bias[lane * 4]);
        float4 o;
        o.x = fmaxf(fmaf(d, acc.x, bb.x), 0.f);
        o.y = fmaxf(fmaf(d, acc.y, bb.y), 0.f);
        o.z = fmaxf(fmaf(d, acc.z, bb.z), 0.f);
        o.w = fmaxf(fmaf(d, acc.w, bb.w), 0.f);
        st_half4(&out[(size_t)node * F + lane * 4], o);
    } else {
        __half2 h = *reinterpret_cast<const __half2*>(&G[(size_t)node * F + lane * 2]);
        float2 acc = __half22float2(h);
        int j = s;
        for (; j + 4 <= e; j += 4) {
            int n0 = g_csr[j], n1 = g_csr[j + 1], n2 = g_csr[j + 2], n3 = g_csr[j + 3];
            float2 v0 = __half22float2(*reinterpret_cast<const __half2*>(&G[(size_t)n0 * F + lane * 2]));
            float2 v1 = __half22float2(*reinterpret_cast<const __half2*>(&G[(size_t)n1 * F + lane * 2]));
            float2 v2 = __half22float2(*reinterpret_cast<const __half2*>(&G[(size_t)n2 * F + lane * 2]));
            float2 v3 = __half22float2(*reinterpret_cast<const __half2*>(&G[(size_t)n3 * F + lane * 2]));
            acc.x += v0.x + v1.x + v2.x + v3.x;
            acc.y += v0.y + v1.y + v2.y + v3.y;
        }
        for (; j < e; j++) {
            float2 v = __half22float2(*reinterpret_cast<const __half2*>(&G[(size_t)g_csr[j] * F + lane * 2]));
            acc.x += v.x; acc.y += v.y;
        }
        float d = g_dinv[node];
        float2 bb = *reinterpret_cast<const float2*>(&bias[lane * 2]);
        float ox = fmaxf(fmaf(d, acc.x, bb.x), 0.f);
        float oy = fmaxf(fmaf(d, acc.y, bb.y), 0.f);
        *reinterpret_cast<__half2*>(&out[(size_t)node * F + lane * 2]) =
            __floats2half2_rn(ox, oy);
    }
}

// ---------------- FP16 tensor-core GEMM (m16n8k16, fp32 accumulate) ----------
__device__ __forceinline__ void mma_f16(float c[4], const unsigned a[4],
                                        const unsigned b[2]) {
    asm volatile(
        "mma.sync.aligned.m16n8k16.row.col.f32.f16.f16.f32 "
        "{%0,%1,%2,%3}, {%4,%5,%6,%7}, {%8,%9}, {%0,%1,%2,%3};"
        : "+f"(c[0]), "+f"(c[1]), "+f"(c[2]), "+f"(c[3])
        : "r"(a[0]), "r"(a[1]), "r"(a[2]), "r"(a[3]), "r"(b[0]), "r"(b[1]));
}

// Core block GEMM. AT: float or __half (A source). CT: float or __half (C dest).
// Tiles staged in smem as half2 (unsigned), row stride 20 (16 half2 + pad) ->
// conflict-free fragment loads (bank = (4r + k2) % 32 all-distinct).
// EPI 0: out = acc * g_dinv[dinvBase+row]
// EPI 1: out = relu(acc + vec[col])
// EPI 3: out = l2norm_row(acc + vec[col])   (F==128, CT=float)
template <int K, int F, int EPI, int LDA, typename AT, typename CT>
__device__ __forceinline__ void gemm_block(
    const AT* __restrict__ A, const float* __restrict__ B,
    const float* __restrict__ vec, CT* __restrict__ C,
    int rowBase, int nRows, int dinvBase) {
    constexpr int BK = 32;            // k per stage (16 half2)
    constexpr int SST = 20;           // smem row stride in half2 units
    constexpr int WN = F / 32;
    constexpr int THREADS = 32 * 2 * WN;
    __shared__ unsigned As2[128 * SST];
    __shared__ unsigned Bs2[F * SST];

    int tid = threadIdx.x;
    int lane = tid & 31;
    int warp = tid >> 5;
    int warpM = warp / WN;
    int warpN = warp % WN;

    float acc[4][4][4];
#pragma unroll
    for (int i = 0; i < 4; i++)
#pragma unroll
        for (int j = 0; j < 4; j++)
#pragma unroll
            for (int q = 0; q < 4; q++) acc[i][j][q] = 0.0f;

    for (int kc = 0; kc < K; kc += BK) {
        // Stage A tile (128 x BK): 4 elements (2 half2) per thread-step
        constexpr int AQ = (128 * BK / 4) / THREADS;
#pragma unroll
        for (int q = 0; q < AQ; q++) {
            int lin = tid + q * THREADS;   // over 128*8 quads
            int r = lin >> 3;
            int k4 = lin & 7;              // quad (4 elems) index
            unsigned p0 = 0, p1 = 0;
            int gr = rowBase + r;
            if (gr < nRows) {
                if constexpr (sizeof(AT) == 4) {
                    float4 v = *reinterpret_cast<const float4*>(
                        &A[(size_t)gr * LDA + kc + k4 * 4]);
                    p0 = pack_half2(v.x, v.y);
                    p1 = pack_half2(v.z, v.w);
                } else {
                    uint2 v = *reinterpret_cast<const uint2*>(
                        &A[(size_t)gr * LDA + kc + k4 * 4]);
                    p0 = v.x; p1 = v.y;
                }
            }
            As2[r * SST + k4 * 2 + 0] = p0;
            As2[r * SST + k4 * 2 + 1] = p1;
        }
        // Stage B tile (BK x F) transposed: Bs2[n][k2] = (B[kc+2k2][n], B[kc+2k2+1][n])
        {
            int n = tid % F;
            int kg = tid / F;                        // 0..1
            constexpr int KPER2 = (BK / 2) / (THREADS / F);  // 8
#pragma unroll
            for (int q = 0; q < KPER2; q++) {
                int k2 = kg * KPER2 + q;
                Bs2[n * SST + k2] = pack_half2(B[(size_t)(kc + 2 * k2) * F + n],
                                               B[(size_t)(kc + 2 * k2 + 1) * F + n]);
            }
        }
        __syncthreads();

#pragma unroll
        for (int ks = 0; ks < BK / 16; ks++) {
            int k2b = ks * 8 + (lane & 3);
            unsigned a[4][4], b[4][2];
            int r0 = warpM * 64 + (lane >> 2);
#pragma unroll
            for (int mf = 0; mf < 4; mf++) {
                int rr = r0 + mf * 16;
                a[mf][0] = As2[rr * SST + k2b];
                a[mf][1] = As2[(rr + 8) * SST + k2b];
                a[mf][2] = As2[rr * SST + k2b + 4];
                a[mf][3] = As2[(rr + 8) * SST + k2b + 4];
            }
            int c0 = warpN * 32 + (lane >> 2);
#pragma unroll
            for (int nf = 0; nf < 4; nf++) {
                b[nf][0] = Bs2[(c0 + nf * 8) * SST + k2b];
                b[nf][1] = Bs2[(c0 + nf * 8) * SST + k2b + 4];
            }
#pragma unroll
            for (int mf = 0; mf < 4; mf++)
#pragma unroll
                for (int nf = 0; nf < 4; nf++) mma_f16(acc[mf][nf], a[mf], b[nf]);
        }
        __syncthreads();
    }

    int cThr = warpN * 32 + (lane & 3) * 2;

    if constexpr (EPI == 3) {
        __shared__ float ss[128];
        if (tid < 128) ss[tid] = 0.f;
        __syncthreads();
#pragma unroll
        for (int mf = 0; mf < 4; mf++) {
#pragma unroll
            for (int half = 0; half < 2; half++) {
                int lr = warpM * 64 + mf * 16 + half * 8 + (lane >> 2);
                float q = 0.f;
#pragma unroll
                for (int nf = 0; nf < 4; nf++) {
                    int gc = cThr + nf * 8;
                    float v0 = acc[mf][nf][half * 2 + 0] + vec[gc];
                    float v1 = acc[mf][nf][half * 2 + 1] + vec[gc + 1];
                    acc[mf][nf][half * 2 + 0] = v0;
                    acc[mf][nf][half * 2 + 1] = v1;
                    q = fmaf(v0, v0, q);
                    q = fmaf(v1, v1, q);
                }
                atomicAdd(&ss[lr], q);
            }
        }
        __syncthreads();
#pragma unroll
        for (int mf = 0; mf < 4; mf++) {
#pragma unroll
            for (int half = 0; half < 2; half++) {
                int lr = warpM * 64 + mf * 16 + half * 8 + (lane >> 2);
                int gr = rowBase + lr;
                if (gr >= nRows) continue;
                float nrm = sqrtf(ss[lr]);
                float inv = 1.0f / fmaxf(nrm, 1e-12f);
#pragma unroll
                for (int nf = 0; nf < 4; nf++) {
                    int gc = cThr + nf * 8;
                    *reinterpret_cast<float2*>(&((float*)C)[(size_t)gr * F + gc]) =
                        make_float2(acc[mf][nf][half * 2 + 0] * inv,
                                    acc[mf][nf][half * 2 + 1] * inv);
                }
            }
        }
    } else {
#pragma unroll
        for (int mf = 0; mf < 4; mf++) {
#pragma unroll
            for (int half = 0; half < 2; half++) {
                int gr = rowBase + warpM * 64 + mf * 16 + half * 8 + (lane >> 2);
                if (gr >= nRows) continue;
                float rs = (EPI == 0) ? g_dinv[dinvBase + gr] : 1.0f;
#pragma unroll
                for (int nf = 0; nf < 4; nf++) {
                    int gc = cThr + nf * 8;
                    float v0 = acc[mf][nf][half * 2 + 0];
                    float v1 = acc[mf][nf][half * 2 + 1];
                    if (EPI == 0) { v0 *= rs; v1 *= rs; }
                    else {
                        v0 += vec[gc]; v1 += vec[gc + 1];
                        if (EPI == 1) { v0 = fmaxf(v0, 0.f); v1 = fmaxf(v1, 0.f); }
                    }
                    if constexpr (sizeof(CT) == 4)
                        *reinterpret_cast<float2*>(&((float*)C)[(size_t)gr * F + gc]) =
                            make_float2(v0, v1);
                    else
                        *reinterpret_cast<__half2*>(&((__half*)C)[(size_t)gr * F + gc]) =
                            __floats2half2_rn(v0, v1);
                }
            }
        }
    }
}

template <int K, int F, int EPI, int LDA, typename AT, typename CT>
__global__ void gemm_tc(const AT* __restrict__ A, const float* __restrict__ B,
                        const float* __restrict__ vec, CT* __restrict__ C,
                        int N2) {
    gemm_block<K, F, EPI, LDA, AT, CT>(A, B, vec, C, blockIdx.x * 128, N2, 0);
}

template <int K, int F, int EPI, int LDA>
__global__ void gemm_tc_dual(const float* __restrict__ A0, const float* __restrict__ A1,
                             const float* __restrict__ B, const float* __restrict__ vec,
                             __half* __restrict__ C, int N) {
    int g = blockIdx.y;
    const float* A = g ? A1 : A0;
    __half* Cg = C + (size_t)g * N * F;
    gemm_block<K, F, EPI, LDA, float, __half>(A, B, vec, Cg, blockIdx.x * 128, N, g * N);
}

// ---------------- fused cluster head: softmax((Hc@Wc2)+bc2) ------------------
__global__ void cluster_kernel(const __half* __restrict__ H,
                               const float* __restrict__ Wc2,
                               const float* __restrict__ bc2,
                               float* __restrict__ out, int N2) {
    int gtid = blockIdx.x * blockDim.x + threadIdx.x;
    int node = gtid >> 5;
    int lane = gtid & 31;
    if (node >= N2) return;
    const __half* rowp = H + (size_t)node * 128 + 64;
    float2 v = __half22float2(*reinterpret_cast<const __half2*>(&rowp[lane * 2]));
    int k0 = lane * 2;
    float d0 = v.x * Wc2[k0 * 3 + 0] + v.y * Wc2[(k0 + 1) * 3 + 0];
    float d1 = v.x * Wc2[k0 * 3 + 1] + v.y * Wc2[(k0 + 1) * 3 + 1];
    float d2 = v.x * Wc2[k0 * 3 + 2] + v.y * Wc2[(k0 + 1) * 3 + 2];
#pragma unroll
    for (int o = 16; o > 0; o >>= 1) {
        d0 += __shfl_down_sync(0xffffffffu, d0, o);
        d1 += __shfl_down_sync(0xffffffffu, d1, o);
        d2 += __shfl_down_sync(0xffffffffu, d2, o);
    }
    if (lane == 0) {
        d0 += bc2[0]; d1 += bc2[1]; d2 += bc2[2];
        float m = fmaxf(d0, fmaxf(d1, d2));
        float e0 = __expf(d0 - m), e1 = __expf(d1 - m), e2 = __expf(d2 - m);
        float inv = 1.0f / (e0 + e1 + e2);
        out[(size_t)node * 3 + 0] = e0 * inv;
        out[(size_t)node * 3 + 1] = e1 * inv;
        out[(size_t)node * 3 + 2] = e2 * inv;
    }
}

// ---------------- launch -----------------------------------------------------
extern "C" void kernel_launch(void* const* d_in, const int* in_sizes, int n_in,
                              void* d_out, int out_size) {
    const float* x1  = (const float*)d_in[0];
    const int*   ei1 = (const int*)  d_in[1];
    const float* x2  = (const float*)d_in[2];
    const int*   ei2 = (const int*)  d_in[3];
    const float* W1  = (const float*)d_in[4];
    const float* b1  = (const float*)d_in[5];
    const float* W2  = (const float*)d_in[6];
    const float* b2  = (const float*)d_in[7];
    const float* Wp1 = (const float*)d_in[8];
    const float* bp1 = (const float*)d_in[9];
    const float* Wp2 = (const float*)d_in[10];
    const float* bp2 = (const float*)d_in[11];
    const float* Wc1 = (const float*)d_in[12];
    const float* bc1 = (const float*)d_in[13];
    const float* Wc2 = (const float*)d_in[14];
    const float* bc2 = (const float*)d_in[15];

    int N = in_sizes[0] / 128;
    int E = in_sizes[1] / 2;
    int N2 = 2 * N;
    int E2 = 2 * E;

    float* out = (float*)d_out;
    float* out_z = out;                       // z_i then z_j, contiguous
    float* out_c = out + (size_t)N2 * 128;    // c_i then c_j, contiguous

    void *pA, *pB, *pC, *pW, *pBi;
    cudaGetSymbolAddress(&pA, g_bufA);
    cudaGetSymbolAddress(&pB, g_bufB);
    cudaGetSymbolAddress(&pC, g_bufC);
    cudaGetSymbolAddress(&pW, g_wcomb);
    cudaGetSymbolAddress(&pBi, g_bcomb);
    __half* bufA = (__half*)pA;
    __half* bufB = (__half*)pB;
    __half* bufC = (__half*)pC;
    float* wcomb = (float*)pW;
    float* bcomb = (float*)pBi;

    int gemmGridN  = (N + 127) / 128;
    int gemmGridN2 = (N2 + 127) / 128;
    int scanBlocks = (N2 + 1023) / 1024;

    combine_wb<<<(64 * 128 + 255) / 256, 256>>>(Wp1, Wc1, bp1, bc1);

    // ---- preprocessing, both graphs batched ----
    zero_deg_kernel<<<(N2 + 255) / 256, 256>>>(N2);
    hist_kernel<<<(E2 + 255) / 256, 256>>>(ei1, ei2, E, N);
    scan_blocks_kernel<<<scanBlocks, 1024>>>(N2);
    scan_top_kernel<<<1, 128>>>(scanBlocks, N2);
    scan_add_kernel<<<(N2 + 255) / 256, 256>>>(N2);
    fill_csr_kernel<<<(E2 + 255) / 256, 256>>>(ei1, ei2, E, N);

    // ---- GCN layer 1 ----
    dim3 grid1(gemmGridN, 2);
    gemm_tc_dual<128, 128, 0, 128><<<grid1, 256>>>(x1, x2, W1, nullptr, bufA, N);
    agg_warp_kernel<128><<<(N2 + 7) / 8, 256>>>(bufA, b1, bufB, N2);

    // ---- GCN layer 2 ----
    gemm_tc<128, 64, 0, 128, __half, __half><<<gemmGridN2, 128>>>(bufB, W2, nullptr, bufA, N2);
    agg_warp_kernel<64><<<(N2 + 7) / 8, 256>>>(bufA, b2, bufC, N2);

    // ---- combined projector: [P | Hc] = relu(Z @ [Wp1|Wc1] + [bp1|bc1]) ----
    gemm_tc<64, 128, 1, 64, __half, __half><<<gemmGridN2, 256>>>(bufC, wcomb, bcomb, bufB, N2);

    // ---- instance head: l2norm(P @ Wp2 + bp2) fused ----
    gemm_tc<64, 128, 3, 128, __half, float><<<gemmGridN2, 256>>>(bufB, Wp2, bp2, out_z, N2);

    // ---- cluster head: softmax(Hc @ Wc2 + bc2) ----
    cluster_kernel<<<((N2 * 32) + 255) / 256, 256>>>(bufB, Wc2, bc2, out_c, N2);
}

// round 8
// speedup vs baseline: 3.2685x; 1.0449x over previous
#include <cuda_runtime.h>
#include <cuda_fp16.h>
#include <math.h>

#define NMAX 50000
#define EMAX 800000
#define N2MAX (2 * NMAX)
#define E2MAX (2 * EMAX)

// ---------------- scratch (static device globals; no allocation) ------------
__device__ __half g_bufA[N2MAX * 128];   // GEMM outputs (pre-agg), fp16
__device__ __half g_bufB[N2MAX * 128];   // agg1 output / projector hidden, fp16
__device__ __half g_bufC[N2MAX * 64];    // encoder output Z, fp16
__device__ float  g_dinv[N2MAX];
__device__ int    g_deg[N2MAX];
__device__ int    g_off[N2MAX + 1];
__device__ int    g_cur[N2MAX];
__device__ int    g_csr[E2MAX];
__device__ int    g_bsum[128];
__device__ int    g_bpre[128];
__device__ float  g_wcomb[64 * 128];   // [Wp1 | Wc1]
__device__ float  g_bcomb[128];        // [bp1 | bc1]

// ---------------- fp16 helpers ----------------------------------------------
__device__ __forceinline__ float4 ld_half4(const __half* p) {
    uint2 r = *reinterpret_cast<const uint2*>(p);
    __half2 h0 = *reinterpret_cast<__half2*>(&r.x);
    __half2 h1 = *reinterpret_cast<__half2*>(&r.y);
    float2 f0 = __half22float2(h0), f1 = __half22float2(h1);
    return make_float4(f0.x, f0.y, f1.x, f1.y);
}
__device__ __forceinline__ void st_half4(__half* p, float4 v) {
    __half2 h0 = __floats2half2_rn(v.x, v.y);
    __half2 h1 = __floats2half2_rn(v.z, v.w);
    uint2 r;
    r.x = *reinterpret_cast<unsigned*>(&h0);
    r.y = *reinterpret_cast<unsigned*>(&h1);
    *reinterpret_cast<uint2*>(p) = r;
}
__device__ __forceinline__ unsigned pack_half2(float a, float b) {
    __half2 h = __floats2half2_rn(a, b);
    return *reinterpret_cast<unsigned*>(&h);
}

// ---------------- weight concat (once per call) ------------------------------
__global__ void combine_wb(const float* __restrict__ Wp1, const float* __restrict__ Wc1,
                           const float* __restrict__ bp1, const float* __restrict__ bc1) {
    int i = blockIdx.x * blockDim.x + threadIdx.x;
    if (i < 64 * 128) {
        int k = i >> 7, n = i & 127;
        g_wcomb[i] = (n < 64) ? Wp1[k * 64 + n] : Wc1[k * 64 + n - 64];
    }
    if (i < 128) g_bcomb[i] = (i < 64) ? bp1[i] : bc1[i - 64];
}

// ---------------- graph preprocessing (both graphs batched) ------------------
__global__ void zero_deg_kernel(int n2) {
    int i = blockIdx.x * blockDim.x + threadIdx.x;
    if (i < n2) g_deg[i] = 0;
}

__global__ void hist_kernel(const int* __restrict__ ei1, const int* __restrict__ ei2,
                            int E, int N) {
    int i = blockIdx.x * blockDim.x + threadIdx.x;
    if (i >= 2 * E) return;
    int g = (i >= E);
    int e = i - g * E;
    const int* ei = g ? ei2 : ei1;
    int c = ei[E + e];
    atomicAdd(&g_deg[g * N + c], 1);
}

__global__ void scan_blocks_kernel(int n2) {
    int b = blockIdx.x, tid = threadIdx.x;
    int i = b * 1024 + tid;
    int lane = tid & 31, w = tid >> 5;
    int v = (i < n2) ? g_deg[i] : 0;
    int s = v;
#pragma unroll
    for (int o = 1; o < 32; o <<= 1) {
        int t = __shfl_up_sync(0xffffffffu, s, o);
        if (lane >= o) s += t;
    }
    __shared__ int wsum[32];
    if (lane == 31) wsum[w] = s;
    __syncthreads();
    if (w == 0) {
        int t = wsum[lane];
#pragma unroll
        for (int o = 1; o < 32; o <<= 1) {
            int u = __shfl_up_sync(0xffffffffu, t, o);
            if (lane >= o) t += u;
        }
        wsum[lane] = t;
    }
    __syncthreads();
    int excl = s - v + (w > 0 ? wsum[w - 1] : 0);
    if (i < n2) {
        g_off[i] = excl;
        g_dinv[i] = rsqrtf((float)(v + 1));
    }
    if (tid == 0) g_bsum[b] = wsum[31];
}

__global__ void scan_top_kernel(int nb, int n2) {
    int tid = threadIdx.x;   // 128
    __shared__ int sh[128];
    int v = (tid < nb) ? g_bsum[tid] : 0;
    sh[tid] = v;
    __syncthreads();
#pragma unroll
    for (int d = 1; d < 128; d <<= 1) {
        int t = (tid >= d) ? sh[tid - d] : 0;
        __syncthreads();
        sh[tid] += t;
        __syncthreads();
    }
    if (tid < nb) g_bpre[tid] = sh[tid] - v;
    if (tid == 127) g_off[n2] = sh[127];
}

__global__ void scan_add_kernel(int n2) {
    int i = blockIdx.x * blockDim.x + threadIdx.x;
    if (i < n2) {
        g_off[i] += g_bpre[i >> 10];
        g_cur[i] = 0;
    }
}

__global__ void fill_csr_kernel(const int* __restrict__ ei1, const int* __restrict__ ei2,
                                int E, int N) {
    int i = blockIdx.x * blockDim.x + threadIdx.x;
    if (i >= 2 * E) return;
    int g = (i >= E);
    int e = i - g * E;
    const int* ei = g ? ei2 : ei1;
    int r = ei[e];
    int c = ei[E + e];
    int cg = g * N + c;
    int p = atomicAdd(&g_cur[cg], 1);
    g_csr[g_off[cg] + p] = g * N + r;
}

// ---------------- neighbor aggregation: warp per node, fp16 rows --------------
// G holds RAW transformed features. Edge norm applied here:
// out[n] = relu( dinv[n] * (dinv[n]*G[n] + sum_j dinv[j]*G[j]) + bias )
template <int F>
__global__ void agg_warp_kernel(const __half* __restrict__ G,
                                const float* __restrict__ bias,
                                __half* __restrict__ out, int N2) {
    int node = blockIdx.x * (blockDim.x >> 5) + (threadIdx.x >> 5);
    if (node >= N2) return;
    int lane = threadIdx.x & 31;
    int s = g_off[node], e = g_off[node + 1];
    float dn = g_dinv[node];

    if constexpr (F == 128) {
        float4 self = ld_half4(&G[(size_t)node * F + lane * 4]);
        float4 acc = make_float4(dn * self.x, dn * self.y, dn * self.z, dn * self.w);
        int j = s;
        for (; j + 4 <= e; j += 4) {
            int n0 = g_csr[j], n1 = g_csr[j + 1], n2 = g_csr[j + 2], n3 = g_csr[j + 3];
            float d0 = g_dinv[n0], d1 = g_dinv[n1], d2 = g_dinv[n2], d3 = g_dinv[n3];
            float4 v0 = ld_half4(&G[(size_t)n0 * F + lane * 4]);
            float4 v1 = ld_half4(&G[(size_t)n1 * F + lane * 4]);
            float4 v2 = ld_half4(&G[(size_t)n2 * F + lane * 4]);
            float4 v3 = ld_half4(&G[(size_t)n3 * F + lane * 4]);
            acc.x += d0 * v0.x + d1 * v1.x + d2 * v2.x + d3 * v3.x;
            acc.y += d0 * v0.y + d1 * v1.y + d2 * v2.y + d3 * v3.y;
            acc.z += d0 * v0.z + d1 * v1.z + d2 * v2.z + d3 * v3.z;
            acc.w += d0 * v0.w + d1 * v1.w + d2 * v2.w + d3 * v3.w;
        }
        for (; j < e; j++) {
            int nj = g_csr[j];
            float dj = g_dinv[nj];
            float4 v = ld_half4(&G[(size_t)nj * F + lane * 4]);
            acc.x = fmaf(dj, v.x, acc.x); acc.y = fmaf(dj, v.y, acc.y);
            acc.z = fmaf(dj, v.z, acc.z); acc.w = fmaf(dj, v.w, acc.w);
        }
        float4 bb = *reinterpret_cast<const float4*>(&bias[lane * 4]);
        float4 o;
        o.x = fmaxf(fmaf(dn, acc.x, bb.x), 0.f);
        o.y = fmaxf(fmaf(dn, acc.y, bb.y), 0.f);
        o.z = fmaxf(fmaf(dn, acc.z, bb.z), 0.f);
        o.w = fmaxf(fmaf(dn, acc.w, bb.w), 0.f);
        st_half4(&out[(size_t)node * F + lane * 4], o);
    } else {
        float2 self = __half22float2(*reinterpret_cast<const __half2*>(&G[(size_t)node * F + lane * 2]));
        float2 acc = make_float2(dn * self.x, dn * self.y);
        int j = s;
        for (; j + 4 <= e; j += 4) {
            int n0 = g_csr[j], n1 = g_csr[j + 1], n2 = g_csr[j + 2], n3 = g_csr[j + 3];
            float d0 = g_dinv[n0], d1 = g_dinv[n1], d2 = g_dinv[n2], d3 = g_dinv[n3];
            float2 v0 = __half22float2(*reinterpret_cast<const __half2*>(&G[(size_t)n0 * F + lane * 2]));
            float2 v1 = __half22float2(*reinterpret_cast<const __half2*>(&G[(size_t)n1 * F + lane * 2]));
            float2 v2 = __half22float2(*reinterpret_cast<const __half2*>(&G[(size_t)n2 * F + lane * 2]));
            float2 v3 = __half22float2(*reinterpret_cast<const __half2*>(&G[(size_t)n3 * F + lane * 2]));
            acc.x += d0 * v0.x + d1 * v1.x + d2 * v2.x + d3 * v3.x;
            acc.y += d0 * v0.y + d1 * v1.y + d2 * v2.y + d3 * v3.y;
        }
        for (; j < e; j++) {
            int nj = g_csr[j];
            float dj = g_dinv[nj];
            float2 v = __half22float2(*reinterpret_cast<const __half2*>(&G[(size_t)nj * F + lane * 2]));
            acc.x = fmaf(dj, v.x, acc.x); acc.y = fmaf(dj, v.y, acc.y);
        }
        float2 bb = *reinterpret_cast<const float2*>(&bias[lane * 2]);
        float ox = fmaxf(fmaf(dn, acc.x, bb.x), 0.f);
        float oy = fmaxf(fmaf(dn, acc.y, bb.y), 0.f);
        *reinterpret_cast<__half2*>(&out[(size_t)node * F + lane * 2]) =
            __floats2half2_rn(ox, oy);
    }
}

// ---------------- FP16 tensor-core GEMM (m16n8k16, fp32 accumulate) ----------
__device__ __forceinline__ void mma_f16(float c[4], const unsigned a[4],
                                        const unsigned b[2]) {
    asm volatile(
        "mma.sync.aligned.m16n8k16.row.col.f32.f16.f16.f32 "
        "{%0,%1,%2,%3}, {%4,%5,%6,%7}, {%8,%9}, {%0,%1,%2,%3};"
        : "+f"(c[0]), "+f"(c[1]), "+f"(c[2]), "+f"(c[3])
        : "r"(a[0]), "r"(a[1]), "r"(a[2]), "r"(a[3]), "r"(b[0]), "r"(b[1]));
}

// EPI 1: out = relu(acc + vec[col])
// EPI 3: out = l2norm_row(acc + vec[col])   (F==128, CT=float)
// EPI 4: out = acc (raw store)
template <int K, int F, int EPI, int LDA, typename AT, typename CT>
__device__ __forceinline__ void gemm_block(
    const AT* __restrict__ A, const float* __restrict__ B,
    const float* __restrict__ vec, CT* __restrict__ C,
    int rowBase, int nRows) {
    constexpr int BK = 32;            // k per stage (16 half2)
    constexpr int SST = 20;           // smem row stride in half2 units
    constexpr int WN = F / 32;
    constexpr int THREADS = 32 * 2 * WN;
    __shared__ unsigned As2[128 * SST];
    __shared__ unsigned Bs2[F * SST];

    int tid = threadIdx.x;
    int lane = tid & 31;
    int warp = tid >> 5;
    int warpM = warp / WN;
    int warpN = warp % WN;

    float acc[4][4][4];
#pragma unroll
    for (int i = 0; i < 4; i++)
#pragma unroll
        for (int j = 0; j < 4; j++)
#pragma unroll
            for (int q = 0; q < 4; q++) acc[i][j][q] = 0.0f;

    for (int kc = 0; kc < K; kc += BK) {
        constexpr int AQ = (128 * BK / 4) / THREADS;
#pragma unroll
        for (int q = 0; q < AQ; q++) {
            int lin = tid + q * THREADS;
            int r = lin >> 3;
            int k4 = lin & 7;
            unsigned p0 = 0, p1 = 0;
            int gr = rowBase + r;
            if (gr < nRows) {
                if constexpr (sizeof(AT) == 4) {
                    float4 v = *reinterpret_cast<const float4*>(
                        &A[(size_t)gr * LDA + kc + k4 * 4]);
                    p0 = pack_half2(v.x, v.y);
                    p1 = pack_half2(v.z, v.w);
                } else {
                    uint2 v = *reinterpret_cast<const uint2*>(
                        &A[(size_t)gr * LDA + kc + k4 * 4]);
                    p0 = v.x; p1 = v.y;
                }
            }
            As2[r * SST + k4 * 2 + 0] = p0;
            As2[r * SST + k4 * 2 + 1] = p1;
        }
        {
            int n = tid % F;
            int kg = tid / F;
            constexpr int KPER2 = (BK / 2) / (THREADS / F);
#pragma unroll
            for (int q = 0; q < KPER2; q++) {
                int k2 = kg * KPER2 + q;
                Bs2[n * SST + k2] = pack_half2(B[(size_t)(kc + 2 * k2) * F + n],
                                               B[(size_t)(kc + 2 * k2 + 1) * F + n]);
            }
        }
        __syncthreads();

#pragma unroll
        for (int ks = 0; ks < BK / 16; ks++) {
            int k2b = ks * 8 + (lane & 3);
            unsigned a[4][4], b[4][2];
            int r0 = warpM * 64 + (lane >> 2);
#pragma unroll
            for (int mf = 0; mf < 4; mf++) {
                int rr = r0 + mf * 16;
                a[mf][0] = As2[rr * SST + k2b];
                a[mf][1] = As2[(rr + 8) * SST + k2b];
                a[mf][2] = As2[rr * SST + k2b + 4];
                a[mf][3] = As2[(rr + 8) * SST + k2b + 4];
            }
            int c0 = warpN * 32 + (lane >> 2);
#pragma unroll
            for (int nf = 0; nf < 4; nf++) {
                b[nf][0] = Bs2[(c0 + nf * 8) * SST + k2b];
                b[nf][1] = Bs2[(c0 + nf * 8) * SST + k2b + 4];
            }
#pragma unroll
            for (int mf = 0; mf < 4; mf++)
#pragma unroll
                for (int nf = 0; nf < 4; nf++) mma_f16(acc[mf][nf], a[mf], b[nf]);
        }
        __syncthreads();
    }

    int cThr = warpN * 32 + (lane & 3) * 2;

    if constexpr (EPI == 3) {
        __shared__ float ss[128];
        if (tid < 128) ss[tid] = 0.f;
        __syncthreads();
#pragma unroll
        for (int mf = 0; mf < 4; mf++) {
#pragma unroll
            for (int half = 0; half < 2; half++) {
                int lr = warpM * 64 + mf * 16 + half * 8 + (lane >> 2);
                float q = 0.f;
#pragma unroll
                for (int nf = 0; nf < 4; nf++) {
                    int gc = cThr + nf * 8;
                    float v0 = acc[mf][nf][half * 2 + 0] + vec[gc];
                    float v1 = acc[mf][nf][half * 2 + 1] + vec[gc + 1];
                    acc[mf][nf][half * 2 + 0] = v0;
                    acc[mf][nf][half * 2 + 1] = v1;
                    q = fmaf(v0, v0, q);
                    q = fmaf(v1, v1, q);
                }
                atomicAdd(&ss[lr], q);
            }
        }
        __syncthreads();
#pragma unroll
        for (int mf = 0; mf < 4; mf++) {
#pragma unroll
            for (int half = 0; half < 2; half++) {
                int lr = warpM * 64 + mf * 16 + half * 8 + (lane >> 2);
                int gr = rowBase + lr;
                if (gr >= nRows) continue;
                float nrm = sqrtf(ss[lr]);
                float inv = 1.0f / fmaxf(nrm, 1e-12f);
#pragma unroll
                for (int nf = 0; nf < 4; nf++) {
                    int gc = cThr + nf * 8;
                    *reinterpret_cast<float2*>(&((float*)C)[(size_t)gr * F + gc]) =
                        make_float2(acc[mf][nf][half * 2 + 0] * inv,
                                    acc[mf][nf][half * 2 + 1] * inv);
                }
            }
        }
    } else {
#pragma unroll
        for (int mf = 0; mf < 4; mf++) {
#pragma unroll
            for (int half = 0; half < 2; half++) {
                int gr = rowBase + warpM * 64 + mf * 16 + half * 8 + (lane >> 2);
                if (gr >= nRows) continue;
#pragma unroll
                for (int nf = 0; nf < 4; nf++) {
                    int gc = cThr + nf * 8;
                    float v0 = acc[mf][nf][half * 2 + 0];
                    float v1 = acc[mf][nf][half * 2 + 1];
                    if (EPI == 1) {
                        v0 = fmaxf(v0 + vec[gc], 0.f);
                        v1 = fmaxf(v1 + vec[gc + 1], 0.f);
                    }
                    if constexpr (sizeof(CT) == 4)
                        *reinterpret_cast<float2*>(&((float*)C)[(size_t)gr * F + gc]) =
                            make_float2(v0, v1);
                    else
                        *reinterpret_cast<__half2*>(&((__half*)C)[(size_t)gr * F + gc]) =
                            __floats2half2_rn(v0, v1);
                }
            }
        }
    }
}

template <int K, int F, int EPI, int LDA, typename AT, typename CT>
__global__ void gemm_tc(const AT* __restrict__ A, const float* __restrict__ B,
                        const float* __restrict__ vec, CT* __restrict__ C,
                        int N2) {
    gemm_block<K, F, EPI, LDA, AT, CT>(A, B, vec, C, blockIdx.x * 128, N2);
}

template <int K, int F, int EPI, int LDA>
__global__ void gemm_tc_dual(const float* __restrict__ A0, const float* __restrict__ A1,
                             const float* __restrict__ B, const float* __restrict__ vec,
                             __half* __restrict__ C, int N) {
    int g = blockIdx.y;
    const float* A = g ? A1 : A0;
    __half* Cg = C + (size_t)g * N * F;
    gemm_block<K, F, EPI, LDA, float, __half>(A, B, vec, Cg, blockIdx.x * 128, N);
}

// ---------------- fused cluster head: softmax((Hc@Wc2)+bc2) ------------------
__global__ void cluster_kernel(const __half* __restrict__ H,
                               const float* __restrict__ Wc2,
                               const float* __restrict__ bc2,
                               float* __restrict__ out, int N2) {
    int gtid = blockIdx.x * blockDim.x + threadIdx.x;
    int node = gtid >> 5;
    int lane = gtid & 31;
    if (node >= N2) return;
    const __half* rowp = H + (size_t)node * 128 + 64;
    float2 v = __half22float2(*reinterpret_cast<const __half2*>(&rowp[lane * 2]));
    int k0 = lane * 2;
    float d0 = v.x * Wc2[k0 * 3 + 0] + v.y * Wc2[(k0 + 1) * 3 + 0];
    float d1 = v.x * Wc2[k0 * 3 + 1] + v.y * Wc2[(k0 + 1) * 3 + 1];
    float d2 = v.x * Wc2[k0 * 3 + 2] + v.y * Wc2[(k0 + 1) * 3 + 2];
#pragma unroll
    for (int o = 16; o > 0; o >>= 1) {
        d0 += __shfl_down_sync(0xffffffffu, d0, o);
        d1 += __shfl_down_sync(0xffffffffu, d1, o);
        d2 += __shfl_down_sync(0xffffffffu, d2, o);
    }
    if (lane == 0) {
        d0 += bc2[0]; d1 += bc2[1]; d2 += bc2[2];
        float m = fmaxf(d0, fmaxf(d1, d2));
        float e0 = __expf(d0 - m), e1 = __expf(d1 - m), e2 = __expf(d2 - m);
        float inv = 1.0f / (e0 + e1 + e2);
        out[(size_t)node * 3 + 0] = e0 * inv;
        out[(size_t)node * 3 + 1] = e1 * inv;
        out[(size_t)node * 3 + 2] = e2 * inv;
    }
}

// ---------------- launch -----------------------------------------------------
extern "C" void kernel_launch(void* const* d_in, const int* in_sizes, int n_in,
                              void* d_out, int out_size) {
    const float* x1  = (const float*)d_in[0];
    const int*   ei1 = (const int*)  d_in[1];
    const float* x2  = (const float*)d_in[2];
    const int*   ei2 = (const int*)  d_in[3];
    const float* W1  = (const float*)d_in[4];
    const float* b1  = (const float*)d_in[5];
    const float* W2  = (const float*)d_in[6];
    const float* b2  = (const float*)d_in[7];
    const float* Wp1 = (const float*)d_in[8];
    const float* bp1 = (const float*)d_in[9];
    const float* Wp2 = (const float*)d_in[10];
    const float* bp2 = (const float*)d_in[11];
    const float* Wc1 = (const float*)d_in[12];
    const float* bc1 = (const float*)d_in[13];
    const float* Wc2 = (const float*)d_in[14];
    const float* bc2 = (const float*)d_in[15];

    int N = in_sizes[0] / 128;
    int E = in_sizes[1] / 2;
    int N2 = 2 * N;
    int E2 = 2 * E;

    float* out = (float*)d_out;
    float* out_z = out;                       // z_i then z_j, contiguous
    float* out_c = out + (size_t)N2 * 128;    // c_i then c_j, contiguous

    void *pA, *pB, *pC, *pW, *pBi;
    cudaGetSymbolAddress(&pA, g_bufA);
    cudaGetSymbolAddress(&pB, g_bufB);
    cudaGetSymbolAddress(&pC, g_bufC);
    cudaGetSymbolAddress(&pW, g_wcomb);
    cudaGetSymbolAddress(&pBi, g_bcomb);
    __half* bufA = (__half*)pA;
    __half* bufB = (__half*)pB;
    __half* bufC = (__half*)pC;
    float* wcomb = (float*)pW;
    float* bcomb = (float*)pBi;

    int gemmGridN  = (N + 127) / 128;
    int gemmGridN2 = (N2 + 127) / 128;
    int scanBlocks = (N2 + 1023) / 1024;

    // One-time side-stream resources (created on first, non-captured call)
    static cudaStream_t s2 = nullptr;
    static cudaEvent_t evFork = nullptr, evJoin = nullptr;
    static cudaEvent_t evFork2 = nullptr, evJoin2 = nullptr;
    if (s2 == nullptr) {
        cudaStreamCreateWithFlags(&s2, cudaStreamNonBlocking);
        cudaEventCreateWithFlags(&evFork, cudaEventDisableTiming);
        cudaEventCreateWithFlags(&evJoin, cudaEventDisableTiming);
        cudaEventCreateWithFlags(&evFork2, cudaEventDisableTiming);
        cudaEventCreateWithFlags(&evJoin2, cudaEventDisableTiming);
    }

    // ---- fork: preprocessing chain on s2 runs concurrently with GEMM-1 ----
    cudaEventRecord(evFork, 0);
    cudaStreamWaitEvent(s2, evFork, 0);

    zero_deg_kernel<<<(N2 + 255) / 256, 256, 0, s2>>>(N2);
    hist_kernel<<<(E2 + 255) / 256, 256, 0, s2>>>(ei1, ei2, E, N);
    scan_blocks_kernel<<<scanBlocks, 1024, 0, s2>>>(N2);
    scan_top_kernel<<<1, 128, 0, s2>>>(scanBlocks, N2);
    scan_add_kernel<<<(N2 + 255) / 256, 256, 0, s2>>>(N2);
    fill_csr_kernel<<<(E2 + 255) / 256, 256, 0, s2>>>(ei1, ei2, E, N);

    // main stream: weight concat + layer-1 GEMM (raw store, graph-independent)
    combine_wb<<<(64 * 128 + 255) / 256, 256>>>(Wp1, Wc1, bp1, bc1);
    dim3 grid1(gemmGridN, 2);
    gemm_tc_dual<128, 128, 4, 128><<<grid1, 256>>>(x1, x2, W1, nullptr, bufA, N);

    // ---- join ----
    cudaEventRecord(evJoin, s2);
    cudaStreamWaitEvent(0, evJoin, 0);

    // ---- GCN layer 1 aggregation (norm fused here) ----
    agg_warp_kernel<128><<<(N2 + 7) / 8, 256>>>(bufA, b1, bufB, N2);

    // ---- GCN layer 2 ----
    gemm_tc<128, 64, 4, 128, __half, __half><<<gemmGridN2, 128>>>(bufB, W2, nullptr, bufA, N2);
    agg_warp_kernel<64><<<(N2 + 7) / 8, 256>>>(bufA, b2, bufC, N2);

    // ---- combined projector: [P | Hc] = relu(Z @ [Wp1|Wc1] + [bp1|bc1]) ----
    gemm_tc<64, 128, 1, 64, __half, __half><<<gemmGridN2, 256>>>(bufC, wcomb, bcomb, bufB, N2);

    // ---- tail fork: cluster head on s2, instance head on main ----
    cudaEventRecord(evFork2, 0);
    cudaStreamWaitEvent(s2, evFork2, 0);

    cluster_kernel<<<((N2 * 32) + 255) / 256, 256, 0, s2>>>(bufB, Wc2, bc2, out_c, N2);
    gemm_tc<64, 128, 3, 128, __half, float><<<gemmGridN2, 256>>>(bufB, Wp2, bp2, out_z, N2);

    cudaEventRecord(evJoin2, s2);
    cudaStreamWaitEvent(0, evJoin2, 0);
}